// round 2
// baseline (speedup 1.0000x reference)
#include <cuda_runtime.h>
#include <math.h>
#include <float.h>

#define NUM_CLASSES 80
#define N_PROP 1000
#define CCH 256
#define ROI 7
#define DFEAT (CCH * ROI * ROI)   // 12544
#define FC 1024
#define SCORE_THR 0.05f
#define IOU_THR 0.5f
#define MAX_DET 100
#define MAX_RATIO 4.135166556742356f  // |log(16/1000)|

// ---------------- device scratch (no cudaMalloc allowed) ----------------
__device__ float g_roi_feats[N_PROP * DFEAT];           // ~50 MB
__device__ float g_h1[N_PROP * FC];
__device__ float g_h2[N_PROP * FC];
__device__ float g_cls[N_PROP * (NUM_CLASSES + 1)];
__device__ float g_reg[N_PROP * NUM_CLASSES * 4];
__device__ float g_scores80[N_PROP * NUM_CLASSES];
__device__ float g_boxes[N_PROP * NUM_CLASSES * 4];
__device__ float g_sorted_boxes[NUM_CLASSES * N_PROP * 4];
__device__ float g_sflat[NUM_CLASSES * N_PROP];

// ---------------- RoI Align ----------------
// one block per roi, 256 threads = 256 channels
__global__ void roi_align_kernel(const float* __restrict__ f0,
                                 const float* __restrict__ f1,
                                 const float* __restrict__ f2,
                                 const float* __restrict__ f3,
                                 const float* __restrict__ props,
                                 float* __restrict__ out) {
    const int n = blockIdx.x;
    const int tid = threadIdx.x;

    __shared__ int sx0[14], sx1[14], sy0[14], sy1[14];
    __shared__ float slx[14], sly[14];
    __shared__ int svx[14], svy[14];

    float px1 = props[n * 4 + 0];
    float py1 = props[n * 4 + 1];
    float px2 = props[n * 4 + 2];
    float py2 = props[n * 4 + 3];
    float w = px2 - px1, h = py2 - py1;
    float sz = sqrtf(fmaxf(w * h, 1e-6f));
    int lvl = (int)floorf(log2f(sz / 56.0f + 1e-6f));
    lvl = lvl < 0 ? 0 : (lvl > 3 ? 3 : lvl);

    const float* feat;
    int H, W;
    if (lvl == 0) { feat = f0; H = 200; W = 336; }
    else if (lvl == 1) { feat = f1; H = 100; W = 168; }
    else if (lvl == 2) { feat = f2; H = 50; W = 84; }
    else { feat = f3; H = 25; W = 42; }
    float scale = 1.0f / (float)(4 << lvl);

    if (tid < 14) {
        int i = tid;
        float pt = ((float)i + 0.5f) / 14.0f;
        // x
        {
            float sx = px1 * scale - 0.5f;
            float rw = w * scale;
            float xs = sx + pt * rw;
            float fx = floorf(xs);
            int x0 = (int)fx; x0 = x0 < 0 ? 0 : (x0 > W - 1 ? W - 1 : x0);
            int x1i = x0 + 1; x1i = x1i > W - 1 ? W - 1 : x1i;
            sx0[i] = x0; sx1[i] = x1i;
            slx[i] = xs - fx;
            svx[i] = (xs >= -1.0f && xs <= (float)W) ? 1 : 0;
        }
        // y
        {
            float sy = py1 * scale - 0.5f;
            float rh = h * scale;
            float ys = sy + pt * rh;
            float fy = floorf(ys);
            int y0 = (int)fy; y0 = y0 < 0 ? 0 : (y0 > H - 1 ? H - 1 : y0);
            int y1i = y0 + 1; y1i = y1i > H - 1 ? H - 1 : y1i;
            sy0[i] = y0; sy1[i] = y1i;
            sly[i] = ys - fy;
            svy[i] = (ys >= -1.0f && ys <= (float)H) ? 1 : 0;
        }
    }
    __syncthreads();

    const int c = tid;
    const float* fc_ = feat + (size_t)c * H * W;
    float* op = out + (size_t)n * DFEAT + (size_t)c * (ROI * ROI);

    #pragma unroll
    for (int py = 0; py < ROI; py++) {
        #pragma unroll
        for (int px = 0; px < ROI; px++) {
            float acc = 0.0f;
            #pragma unroll
            for (int sy = 0; sy < 2; sy++) {
                int iy = py * 2 + sy;
                int y0 = sy0[iy], y1v = sy1[iy];
                float ly = sly[iy];
                int vy = svy[iy];
                #pragma unroll
                for (int sxs = 0; sxs < 2; sxs++) {
                    int ix = px * 2 + sxs;
                    if (vy && svx[ix]) {
                        int x0 = sx0[ix], x1v = sx1[ix];
                        float lx = slx[ix];
                        float v00 = fc_[y0 * W + x0];
                        float v01 = fc_[y0 * W + x1v];
                        float v10 = fc_[y1v * W + x0];
                        float v11 = fc_[y1v * W + x1v];
                        float top = (1.0f - lx) * v00 + lx * v01;
                        float bot = (1.0f - lx) * v10 + lx * v11;
                        acc += (1.0f - ly) * top + ly * bot;
                    }
                }
            }
            op[py * ROI + px] = acc * 0.25f;
        }
    }
}

// ---------------- GEMM: C[M,N] = A[M,K] @ B[N,K]^T + bias, opt relu ----
// BM=64, BN=128, BK=16, 256 threads, thread tile 8(m) x 4(n)
__global__ void gemm_bias_kernel(const float* __restrict__ A,
                                 const float* __restrict__ B,
                                 const float* __restrict__ bias,
                                 float* __restrict__ C,
                                 int M, int N, int K, int relu) {
    const int BM = 64, BN = 128, BK = 16;
    __shared__ float As[16][BM + 4];
    __shared__ float Bs[16][BN + 4];

    const int tid = threadIdx.x;
    const int m0 = blockIdx.y * BM;
    const int n0 = blockIdx.x * BN;
    const int tx = tid & 31;      // n dim
    const int ty = tid >> 5;      // m dim (0..7)

    const int aRow = tid >> 2;
    const int aK = (tid & 3) * 4;

    float acc[8][4];
    #pragma unroll
    for (int i = 0; i < 8; i++)
        #pragma unroll
        for (int j = 0; j < 4; j++) acc[i][j] = 0.0f;

    for (int k0 = 0; k0 < K; k0 += BK) {
        // load A tile (64x16)
        float4 av = make_float4(0.f, 0.f, 0.f, 0.f);
        if (m0 + aRow < M)
            av = *(const float4*)&A[(size_t)(m0 + aRow) * K + k0 + aK];
        As[aK + 0][aRow] = av.x;
        As[aK + 1][aRow] = av.y;
        As[aK + 2][aRow] = av.z;
        As[aK + 3][aRow] = av.w;
        // load B tile (128x16)
        #pragma unroll
        for (int r = 0; r < 2; r++) {
            int idx = tid + r * 256;
            int bRow = idx >> 2;
            int bK = (idx & 3) * 4;
            float4 bv = make_float4(0.f, 0.f, 0.f, 0.f);
            if (n0 + bRow < N)
                bv = *(const float4*)&B[(size_t)(n0 + bRow) * K + k0 + bK];
            Bs[bK + 0][bRow] = bv.x;
            Bs[bK + 1][bRow] = bv.y;
            Bs[bK + 2][bRow] = bv.z;
            Bs[bK + 3][bRow] = bv.w;
        }
        __syncthreads();

        #pragma unroll
        for (int kk = 0; kk < BK; kk++) {
            float4 a0 = *(const float4*)&As[kk][ty * 8];
            float4 a1 = *(const float4*)&As[kk][ty * 8 + 4];
            float4 b = *(const float4*)&Bs[kk][tx * 4];
            float am[8] = {a0.x, a0.y, a0.z, a0.w, a1.x, a1.y, a1.z, a1.w};
            float bn_[4] = {b.x, b.y, b.z, b.w};
            #pragma unroll
            for (int i = 0; i < 8; i++)
                #pragma unroll
                for (int j = 0; j < 4; j++)
                    acc[i][j] += am[i] * bn_[j];
        }
        __syncthreads();
    }

    #pragma unroll
    for (int i = 0; i < 8; i++) {
        int m = m0 + ty * 8 + i;
        if (m >= M) continue;
        #pragma unroll
        for (int j = 0; j < 4; j++) {
            int n = n0 + tx * 4 + j;
            if (n >= N) continue;
            float v = acc[i][j] + bias[n];
            if (relu) v = fmaxf(v, 0.0f);
            C[(size_t)m * N + n] = v;
        }
    }
}

// ---------------- softmax + delta2bbox ----------------
__global__ void head_kernel(const float* __restrict__ cls,
                            const float* __restrict__ reg,
                            const float* __restrict__ props,
                            float* __restrict__ scores80,
                            float* __restrict__ boxes) {
    const int n = blockIdx.x;
    const int tid = threadIdx.x;
    __shared__ float sv[81];
    __shared__ float red[128];

    float v = (tid < 81) ? cls[n * 81 + tid] : -FLT_MAX;
    if (tid < 81) sv[tid] = v;
    red[tid] = v;
    __syncthreads();
    for (int s = 64; s > 0; s >>= 1) {
        if (tid < s) red[tid] = fmaxf(red[tid], red[tid + s]);
        __syncthreads();
    }
    float mx = red[0];
    __syncthreads();
    float e = (tid < 81) ? expf(sv[tid] - mx) : 0.0f;
    red[tid] = e;
    __syncthreads();
    for (int s = 64; s > 0; s >>= 1) {
        if (tid < s) red[tid] += red[tid + s];
        __syncthreads();
    }
    float sum = red[0];

    if (tid < NUM_CLASSES)
        scores80[n * NUM_CLASSES + tid] = e / sum;

    if (tid < NUM_CLASSES) {
        const float* rp = reg + (size_t)n * NUM_CLASSES * 4 + tid * 4;
        float dx = rp[0] * 0.1f;
        float dy = rp[1] * 0.1f;
        float dw = fminf(fmaxf(rp[2] * 0.2f, -MAX_RATIO), MAX_RATIO);
        float dh = fminf(fmaxf(rp[3] * 0.2f, -MAX_RATIO), MAX_RATIO);
        float p0 = props[n * 4 + 0], p1 = props[n * 4 + 1];
        float p2 = props[n * 4 + 2], p3 = props[n * 4 + 3];
        float pcx = (p0 + p2) * 0.5f;
        float pcy = (p1 + p3) * 0.5f;
        float pw = p2 - p0, ph = p3 - p1;
        float gw = pw * expf(dw);
        float gh = ph * expf(dh);
        float gx = pcx + pw * dx;
        float gy = pcy + ph * dy;
        float* bp = boxes + ((size_t)n * NUM_CLASSES + tid) * 4;
        bp[0] = gx - gw * 0.5f;
        bp[1] = gy - gh * 0.5f;
        bp[2] = gx + gw * 0.5f;
        bp[3] = gy + gh * 0.5f;
    }
}

// ---------------- per-class NMS (80 blocks) ----------------
__global__ void nms_kernel(const float* __restrict__ scores80,
                           const float* __restrict__ boxesAll,
                           float* __restrict__ sortedBoxes,
                           float* __restrict__ sflat) {
    const int c = blockIdx.x;
    const int tid = threadIdx.x;
    const int NT = 256;

    __shared__ float skey[1024];
    __shared__ int sidx[1024];
    __shared__ float4 sbox[N_PROP];
    __shared__ float sarea[N_PROP];
    __shared__ unsigned char keep[N_PROP];

    for (int j = tid; j < 1024; j += NT) {
        skey[j] = (j < N_PROP) ? scores80[j * NUM_CLASSES + c] : -FLT_MAX;
        sidx[j] = j;
    }

    // bitonic sort by (score desc, idx asc)
    for (int k = 2; k <= 1024; k <<= 1) {
        for (int j = k >> 1; j > 0; j >>= 1) {
            __syncthreads();
            for (int i = tid; i < 1024; i += NT) {
                int ixj = i ^ j;
                if (ixj > i) {
                    float si = skey[i], sx = skey[ixj];
                    int ii = sidx[i], ix = sidx[ixj];
                    bool x_first = (sx > si) || (sx == si && ix < ii);
                    bool up = ((i & k) == 0);
                    bool swp = up ? x_first : !x_first;
                    if (swp) {
                        skey[i] = sx; skey[ixj] = si;
                        sidx[i] = ix; sidx[ixj] = ii;
                    }
                }
            }
        }
    }
    __syncthreads();

    // gather boxes in sorted order, precompute areas, init keep
    for (int j = tid; j < N_PROP; j += NT) {
        int oi = sidx[j];
        float4 b = *(const float4*)&boxesAll[((size_t)oi * NUM_CLASSES + c) * 4];
        sbox[j] = b;
        sarea[j] = fmaxf(b.z - b.x, 0.0f) * fmaxf(b.w - b.y, 0.0f);
        keep[j] = (skey[j] > SCORE_THR) ? 1 : 0;
    }
    __syncthreads();

    // greedy suppression (sorted => break once below threshold)
    for (int i = 0; i < N_PROP; i++) {
        if (skey[i] <= SCORE_THR) break;   // uniform (shared)
        __syncthreads();
        if (keep[i]) {
            float4 bi = sbox[i];
            float ai = sarea[i];
            for (int j = i + 1 + tid; j < N_PROP; j += NT) {
                if (!keep[j]) continue;
                float4 bj = sbox[j];
                float iw = fminf(bi.z, bj.z) - fmaxf(bi.x, bj.x);
                float ih = fminf(bi.w, bj.w) - fmaxf(bi.y, bj.y);
                iw = fmaxf(iw, 0.0f);
                ih = fmaxf(ih, 0.0f);
                float inter = iw * ih;
                float iou = inter / fmaxf(ai + sarea[j] - inter, 1e-8f);
                if (iou > IOU_THR) keep[j] = 0;
            }
        }
    }
    __syncthreads();

    for (int j = tid; j < N_PROP; j += NT) {
        sflat[c * N_PROP + j] = keep[j] ? skey[j] : -1.0f;
        *(float4*)&sortedBoxes[((size_t)c * N_PROP + j) * 4] = sbox[j];
    }
}

// ---------------- top-k + output assembly (1 block) ----------------
__global__ void topk_kernel(float* __restrict__ sflat,
                            const float* __restrict__ sortedBoxes,
                            float* __restrict__ out,
                            int out_size) {
    const int tid = threadIdx.x;
    const int NT = 1024;
    const int TOT = NUM_CLASSES * N_PROP;

    __shared__ float rv[1024];
    __shared__ int ri[1024];
    __shared__ float topv[MAX_DET];
    __shared__ int topi[MAX_DET];

    for (int sel = 0; sel < MAX_DET; sel++) {
        float bv = -FLT_MAX;
        int bi = 0x7fffffff;
        for (int j = tid; j < TOT; j += NT) {
            float v = sflat[j];
            if (v > bv || (v == bv && j < bi)) { bv = v; bi = j; }
        }
        rv[tid] = bv;
        ri[tid] = bi;
        __syncthreads();
        for (int s = 512; s > 0; s >>= 1) {
            if (tid < s) {
                float ov = rv[tid + s];
                int oi = ri[tid + s];
                if (ov > rv[tid] || (ov == rv[tid] && oi < ri[tid])) {
                    rv[tid] = ov; ri[tid] = oi;
                }
            }
            __syncthreads();
        }
        if (tid == 0) {
            topv[sel] = rv[0];
            topi[sel] = ri[0];
            sflat[ri[0]] = -FLT_MAX;
        }
        __syncthreads();
    }

    // num_det
    if (tid == 0) {
        int nd = 0;
        for (int k = 0; k < MAX_DET; k++)
            if (topv[k] > 0.0f) nd++;
        if (out_size > 0) out[0] = (float)nd;
    }
    __syncthreads();

    for (int k = tid; k < MAX_DET; k += NT) {
        bool valid = topv[k] > 0.0f;
        int oi = topi[k];
        float b0 = 0.f, b1 = 0.f, b2 = 0.f, b3 = 0.f;
        if (valid) {
            const float* bp = &sortedBoxes[(size_t)oi * 4];
            b0 = bp[0]; b1 = bp[1]; b2 = bp[2]; b3 = bp[3];
        }
        if (1 + k * 4 + 3 < out_size) {
            out[1 + k * 4 + 0] = b0;
            out[1 + k * 4 + 1] = b1;
            out[1 + k * 4 + 2] = b2;
            out[1 + k * 4 + 3] = b3;
        }
        if (401 + k < out_size) out[401 + k] = valid ? topv[k] : 0.0f;
        if (501 + k < out_size) out[501 + k] = valid ? (float)(oi / N_PROP) : -1.0f;
    }
    // zero any tail beyond expected layout
    for (int i = 601 + tid; i < out_size; i += NT) out[i] = 0.0f;
}

// ---------------- launch ----------------
extern "C" void kernel_launch(void* const* d_in, const int* in_sizes, int n_in,
                              void* d_out, int out_size) {
    const float* f0 = (const float*)d_in[0];
    const float* f1 = (const float*)d_in[1];
    const float* f2 = (const float*)d_in[2];
    const float* f3 = (const float*)d_in[3];
    const float* props = (const float*)d_in[4];
    const float* fc1_w = (const float*)d_in[5];
    const float* fc1_b = (const float*)d_in[6];
    const float* fc2_w = (const float*)d_in[7];
    const float* fc2_b = (const float*)d_in[8];
    const float* cls_w = (const float*)d_in[9];
    const float* cls_b = (const float*)d_in[10];
    const float* reg_w = (const float*)d_in[11];
    const float* reg_b = (const float*)d_in[12];
    float* out = (float*)d_out;

    float *roi_feats, *h1, *h2, *clsb, *regb, *sc80, *boxes, *sboxes, *sflat;
    cudaGetSymbolAddress((void**)&roi_feats, g_roi_feats);
    cudaGetSymbolAddress((void**)&h1, g_h1);
    cudaGetSymbolAddress((void**)&h2, g_h2);
    cudaGetSymbolAddress((void**)&clsb, g_cls);
    cudaGetSymbolAddress((void**)&regb, g_reg);
    cudaGetSymbolAddress((void**)&sc80, g_scores80);
    cudaGetSymbolAddress((void**)&boxes, g_boxes);
    cudaGetSymbolAddress((void**)&sboxes, g_sorted_boxes);
    cudaGetSymbolAddress((void**)&sflat, g_sflat);

    roi_align_kernel<<<N_PROP, 256>>>(f0, f1, f2, f3, props, roi_feats);

    {
        dim3 grid((FC + 127) / 128, (N_PROP + 63) / 64);
        gemm_bias_kernel<<<grid, 256>>>(roi_feats, fc1_w, fc1_b, h1,
                                        N_PROP, FC, DFEAT, 1);
    }
    {
        dim3 grid((FC + 127) / 128, (N_PROP + 63) / 64);
        gemm_bias_kernel<<<grid, 256>>>(h1, fc2_w, fc2_b, h2,
                                        N_PROP, FC, FC, 1);
    }
    {
        dim3 grid((81 + 127) / 128, (N_PROP + 63) / 64);
        gemm_bias_kernel<<<grid, 256>>>(h2, cls_w, cls_b, clsb,
                                        N_PROP, 81, FC, 0);
    }
    {
        dim3 grid((NUM_CLASSES * 4 + 127) / 128, (N_PROP + 63) / 64);
        gemm_bias_kernel<<<grid, 256>>>(h2, reg_w, reg_b, regb,
                                        N_PROP, NUM_CLASSES * 4, FC, 0);
    }

    head_kernel<<<N_PROP, 128>>>(clsb, regb, props, sc80, boxes);
    nms_kernel<<<NUM_CLASSES, 256>>>(sc80, boxes, sboxes, sflat);
    topk_kernel<<<1, 1024>>>(sflat, sboxes, out, out_size);
}

// round 4
// speedup vs baseline: 4.1213x; 4.1213x over previous
#include <cuda_runtime.h>
#include <cuda_bf16.h>
#include <math.h>
#include <float.h>
#include <stdint.h>

#define NUM_CLASSES 80
#define N_PROP 1000
#define CCH 256
#define ROI 7
#define DFEAT (CCH * ROI * ROI)   // 12544
#define FC 1024
#define NHEAD 401                  // 81 cls + 320 reg
#define SCORE_THR 0.05f
#define IOU_THR 0.5f
#define MAX_DET 100
#define MAX_RATIO 4.135166556742356f  // |log(16/1000)|

// ---------------- device scratch (no cudaMalloc allowed) ----------------
__device__ float g_f0t[200 * 336 * CCH];   // NHWC transposed features
__device__ float g_f1t[100 * 168 * CCH];
__device__ float g_f2t[50 * 84 * CCH];
__device__ float g_f3t[25 * 42 * CCH];

__device__ __nv_bfloat16 g_roi_feats[N_PROP * DFEAT];
__device__ __nv_bfloat16 g_h1[N_PROP * FC];
__device__ __nv_bfloat16 g_h2[N_PROP * FC];
__device__ __nv_bfloat16 g_fc1w[FC * DFEAT];
__device__ __nv_bfloat16 g_fc2w[FC * FC];
__device__ __nv_bfloat16 g_headw[NHEAD * FC];
__device__ float g_headb[NHEAD];
__device__ float g_head_out[N_PROP * NHEAD];

__device__ float g_scores80[N_PROP * NUM_CLASSES];
__device__ float g_boxes[N_PROP * NUM_CLASSES * 4];
__device__ float g_sorted_boxes[NUM_CLASSES * N_PROP * 4];
__device__ float g_sflat[NUM_CLASSES * N_PROP];

__device__ int g_ncand;
__device__ float g_cand_v[NUM_CLASSES * N_PROP];
__device__ int   g_cand_i[NUM_CLASSES * N_PROP];

// ---------------- NCHW -> NHWC transpose (treat as 2D transpose C x HW) ----
__global__ void nchw2nhwc_kernel(const float* __restrict__ in,
                                 float* __restrict__ out, int HW) {
    __shared__ float t[32][33];
    int hw0 = blockIdx.x * 32;
    int c0 = blockIdx.y * 32;
    int x = hw0 + threadIdx.x;
    #pragma unroll
    for (int i = 0; i < 32; i += 8) {
        int c = c0 + threadIdx.y + i;
        if (x < HW) t[threadIdx.y + i][threadIdx.x] = in[(size_t)c * HW + x];
    }
    __syncthreads();
    int co = c0 + threadIdx.x;
    #pragma unroll
    for (int i = 0; i < 32; i += 8) {
        int xo = hw0 + threadIdx.y + i;
        if (xo < HW) out[(size_t)xo * CCH + co] = t[threadIdx.x][threadIdx.y + i];
    }
}

// ---------------- RoI Align (NHWC input, bf16 output) ----------------
__global__ void roi_align_kernel(const float* __restrict__ f0,
                                 const float* __restrict__ f1,
                                 const float* __restrict__ f2,
                                 const float* __restrict__ f3,
                                 const float* __restrict__ props,
                                 __nv_bfloat16* __restrict__ out) {
    const int n = blockIdx.x;
    const int tid = threadIdx.x;

    __shared__ int sx0[14], sx1[14], sy0[14], sy1[14];
    __shared__ float slx[14], sly[14];
    __shared__ int svx[14], svy[14];

    float px1 = props[n * 4 + 0];
    float py1 = props[n * 4 + 1];
    float px2 = props[n * 4 + 2];
    float py2 = props[n * 4 + 3];
    float w = px2 - px1, h = py2 - py1;
    float sz = sqrtf(fmaxf(w * h, 1e-6f));
    int lvl = (int)floorf(log2f(sz / 56.0f + 1e-6f));
    lvl = lvl < 0 ? 0 : (lvl > 3 ? 3 : lvl);

    const float* feat;
    int H, W;
    if (lvl == 0) { feat = f0; H = 200; W = 336; }
    else if (lvl == 1) { feat = f1; H = 100; W = 168; }
    else if (lvl == 2) { feat = f2; H = 50; W = 84; }
    else { feat = f3; H = 25; W = 42; }
    float scale = 1.0f / (float)(4 << lvl);

    if (tid < 14) {
        int i = tid;
        float pt = ((float)i + 0.5f) / 14.0f;
        {
            float sx = px1 * scale - 0.5f;
            float xs = sx + pt * (w * scale);
            float fx = floorf(xs);
            int x0 = (int)fx; x0 = x0 < 0 ? 0 : (x0 > W - 1 ? W - 1 : x0);
            int x1i = x0 + 1; x1i = x1i > W - 1 ? W - 1 : x1i;
            sx0[i] = x0; sx1[i] = x1i;
            slx[i] = xs - fx;
            svx[i] = (xs >= -1.0f && xs <= (float)W) ? 1 : 0;
        }
        {
            float sy = py1 * scale - 0.5f;
            float ys = sy + pt * (h * scale);
            float fy = floorf(ys);
            int y0 = (int)fy; y0 = y0 < 0 ? 0 : (y0 > H - 1 ? H - 1 : y0);
            int y1i = y0 + 1; y1i = y1i > H - 1 ? H - 1 : y1i;
            sy0[i] = y0; sy1[i] = y1i;
            sly[i] = ys - fy;
            svy[i] = (ys >= -1.0f && ys <= (float)H) ? 1 : 0;
        }
    }
    __syncthreads();

    const int c = tid;   // 256 threads = 256 channels; NHWC => coalesced
    __nv_bfloat16* op = out + (size_t)n * DFEAT + (size_t)c * (ROI * ROI);

    #pragma unroll
    for (int py = 0; py < ROI; py++) {
        #pragma unroll
        for (int px = 0; px < ROI; px++) {
            float acc = 0.0f;
            #pragma unroll
            for (int sy = 0; sy < 2; sy++) {
                int iy = py * 2 + sy;
                int y0 = sy0[iy], y1v = sy1[iy];
                float ly = sly[iy];
                int vy = svy[iy];
                #pragma unroll
                for (int sxs = 0; sxs < 2; sxs++) {
                    int ix = px * 2 + sxs;
                    if (vy && svx[ix]) {
                        int x0 = sx0[ix], x1v = sx1[ix];
                        float lx = slx[ix];
                        float v00 = feat[((size_t)(y0 * W + x0) << 8) + c];
                        float v01 = feat[((size_t)(y0 * W + x1v) << 8) + c];
                        float v10 = feat[((size_t)(y1v * W + x0) << 8) + c];
                        float v11 = feat[((size_t)(y1v * W + x1v) << 8) + c];
                        float top = (1.0f - lx) * v00 + lx * v01;
                        float bot = (1.0f - lx) * v10 + lx * v11;
                        acc += (1.0f - ly) * top + ly * bot;
                    }
                }
            }
            op[py * ROI + px] = __float2bfloat16(acc * 0.25f);
        }
    }
}

// ---------------- weight conversions ----------------
__global__ void cvt_bf16_kernel(const float* __restrict__ s,
                                __nv_bfloat16* __restrict__ d, int n4) {
    int i = blockIdx.x * blockDim.x + threadIdx.x;
    if (i < n4) {
        float4 v = ((const float4*)s)[i];
        __nv_bfloat162 lo = __floats2bfloat162_rn(v.x, v.y);
        __nv_bfloat162 hi = __floats2bfloat162_rn(v.z, v.w);
        ((__nv_bfloat162*)d)[2 * i] = lo;
        ((__nv_bfloat162*)d)[2 * i + 1] = hi;
    }
}

__global__ void build_head_kernel(const float* __restrict__ cls_w,
                                  const float* __restrict__ reg_w,
                                  const float* __restrict__ cls_b,
                                  const float* __restrict__ reg_b,
                                  __nv_bfloat16* __restrict__ wout,
                                  float* __restrict__ bout) {
    int i = blockIdx.x * blockDim.x + threadIdx.x;
    const int total = NHEAD * FC;
    if (i < total) {
        int r = i >> 10, k = i & 1023;
        float v = (r < 81) ? cls_w[r * FC + k] : reg_w[(r - 81) * FC + k];
        wout[i] = __float2bfloat16(v);
    }
    if (i < NHEAD) bout[i] = (i < 81) ? cls_b[i] : reg_b[i - 81];
}

// ---------------- bf16 tensor-core GEMM: C[M,N] = A[M,K] @ B[N,K]^T + bias --
// BM=128, BN=64, BK=32; 256 threads = 8 warps (4m x 2n), warp tile 32m x 32n
__device__ __forceinline__ void mma16816(float* c, const uint32_t* a, const uint32_t* b) {
    asm volatile(
        "mma.sync.aligned.m16n8k16.row.col.f32.bf16.bf16.f32 "
        "{%0,%1,%2,%3},{%4,%5,%6,%7},{%8,%9},{%0,%1,%2,%3};"
        : "+f"(c[0]), "+f"(c[1]), "+f"(c[2]), "+f"(c[3])
        : "r"(a[0]), "r"(a[1]), "r"(a[2]), "r"(a[3]), "r"(b[0]), "r"(b[1]));
}

__global__ __launch_bounds__(256, 2)
void gemm_bf16_kernel(const __nv_bfloat16* __restrict__ A,
                      const __nv_bfloat16* __restrict__ B,
                      const float* __restrict__ bias,
                      void* __restrict__ Cout,
                      int M, int N, int K, int relu, int out_bf16) {
    const int BM = 128, BN = 64, BK = 32;
    __shared__ __nv_bfloat16 As[128][40];
    __shared__ __nv_bfloat16 Bs[64][40];

    const int tid = threadIdx.x;
    const int warp = tid >> 5, lane = tid & 31;
    const int wm = warp >> 1, wn = warp & 1;
    const int g = lane >> 2, tg = lane & 3;
    const int m0 = blockIdx.y * BM, n0 = blockIdx.x * BN;

    const int aRow = tid >> 2;            // + 64*r
    const int kc = (tid & 3) * 8;

    float acc[2][4][4];
    #pragma unroll
    for (int i = 0; i < 2; i++)
        #pragma unroll
        for (int j = 0; j < 4; j++)
            #pragma unroll
            for (int q = 0; q < 4; q++) acc[i][j][q] = 0.0f;

    const uint4 z4 = make_uint4(0u, 0u, 0u, 0u);
    uint4 pa[2], pb;
    {
        int r0 = m0 + aRow, r1 = m0 + aRow + 64;
        pa[0] = (r0 < M) ? *(const uint4*)&A[(size_t)r0 * K + kc] : z4;
        pa[1] = (r1 < M) ? *(const uint4*)&A[(size_t)r1 * K + kc] : z4;
        int br = n0 + aRow;
        pb = (br < N && aRow < 64) ? *(const uint4*)&B[(size_t)br * K + kc] : z4;
    }

    for (int k0 = 0; k0 < K; k0 += BK) {
        *(uint4*)&As[aRow][kc] = pa[0];
        *(uint4*)&As[aRow + 64][kc] = pa[1];
        if (aRow < 64) *(uint4*)&Bs[aRow][kc] = pb;
        __syncthreads();

        int kn = k0 + BK;
        if (kn < K) {
            int r0 = m0 + aRow, r1 = m0 + aRow + 64;
            pa[0] = (r0 < M) ? *(const uint4*)&A[(size_t)r0 * K + kn + kc] : z4;
            pa[1] = (r1 < M) ? *(const uint4*)&A[(size_t)r1 * K + kn + kc] : z4;
            int br = n0 + aRow;
            pb = (br < N && aRow < 64) ? *(const uint4*)&B[(size_t)br * K + kn + kc] : z4;
        }

        #pragma unroll
        for (int ks = 0; ks < 2; ks++) {
            const int kb = ks * 16;
            uint32_t af[2][4], bf[4][2];
            #pragma unroll
            for (int mt = 0; mt < 2; mt++) {
                int row = wm * 32 + mt * 16;
                af[mt][0] = *(const uint32_t*)&As[row + g][kb + tg * 2];
                af[mt][1] = *(const uint32_t*)&As[row + g + 8][kb + tg * 2];
                af[mt][2] = *(const uint32_t*)&As[row + g][kb + tg * 2 + 8];
                af[mt][3] = *(const uint32_t*)&As[row + g + 8][kb + tg * 2 + 8];
            }
            #pragma unroll
            for (int nt = 0; nt < 4; nt++) {
                int col = wn * 32 + nt * 8 + g;
                bf[nt][0] = *(const uint32_t*)&Bs[col][kb + tg * 2];
                bf[nt][1] = *(const uint32_t*)&Bs[col][kb + tg * 2 + 8];
            }
            #pragma unroll
            for (int mt = 0; mt < 2; mt++)
                #pragma unroll
                for (int nt = 0; nt < 4; nt++)
                    mma16816(acc[mt][nt], af[mt], bf[nt]);
        }
        __syncthreads();
    }

    // epilogue
    #pragma unroll
    for (int mt = 0; mt < 2; mt++) {
        #pragma unroll
        for (int nt = 0; nt < 4; nt++) {
            int n = n0 + wn * 32 + nt * 8 + tg * 2;
            if (n >= N) continue;
            float b0 = bias[n];
            float b1 = (n + 1 < N) ? bias[n + 1] : 0.0f;
            #pragma unroll
            for (int rh = 0; rh < 2; rh++) {
                int m = m0 + wm * 32 + mt * 16 + g + rh * 8;
                if (m >= M) continue;
                float v0 = acc[mt][nt][rh * 2 + 0] + b0;
                float v1 = acc[mt][nt][rh * 2 + 1] + b1;
                if (relu) { v0 = fmaxf(v0, 0.0f); v1 = fmaxf(v1, 0.0f); }
                if (out_bf16) {
                    __nv_bfloat16* C = (__nv_bfloat16*)Cout;
                    if (n + 1 < N) {
                        *(__nv_bfloat162*)&C[(size_t)m * N + n] = __floats2bfloat162_rn(v0, v1);
                    } else {
                        C[(size_t)m * N + n] = __float2bfloat16(v0);
                    }
                } else {
                    float* C = (float*)Cout;
                    C[(size_t)m * N + n] = v0;
                    if (n + 1 < N) C[(size_t)m * N + n + 1] = v1;
                }
            }
        }
    }
}

// ---------------- softmax + delta2bbox ----------------
__global__ void head_kernel(const float* __restrict__ head_out,
                            const float* __restrict__ props,
                            float* __restrict__ scores80,
                            float* __restrict__ boxes) {
    const int n = blockIdx.x;
    const int tid = threadIdx.x;
    __shared__ float sv[81];
    __shared__ float red[128];

    const float* row = head_out + (size_t)n * NHEAD;
    float v = (tid < 81) ? row[tid] : -FLT_MAX;
    if (tid < 81) sv[tid] = v;
    red[tid] = v;
    __syncthreads();
    for (int s = 64; s > 0; s >>= 1) {
        if (tid < s) red[tid] = fmaxf(red[tid], red[tid + s]);
        __syncthreads();
    }
    float mx = red[0];
    __syncthreads();
    float e = (tid < 81) ? expf(sv[tid] - mx) : 0.0f;
    red[tid] = e;
    __syncthreads();
    for (int s = 64; s > 0; s >>= 1) {
        if (tid < s) red[tid] += red[tid + s];
        __syncthreads();
    }
    float sum = red[0];

    if (tid < NUM_CLASSES) {
        scores80[n * NUM_CLASSES + tid] = e / sum;

        const float* rp = row + 81 + tid * 4;
        float dx = rp[0] * 0.1f;
        float dy = rp[1] * 0.1f;
        float dw = fminf(fmaxf(rp[2] * 0.2f, -MAX_RATIO), MAX_RATIO);
        float dh = fminf(fmaxf(rp[3] * 0.2f, -MAX_RATIO), MAX_RATIO);
        float p0 = props[n * 4 + 0], p1 = props[n * 4 + 1];
        float p2 = props[n * 4 + 2], p3 = props[n * 4 + 3];
        float pcx = (p0 + p2) * 0.5f;
        float pcy = (p1 + p3) * 0.5f;
        float pw = p2 - p0, ph = p3 - p1;
        float gw = pw * expf(dw);
        float gh = ph * expf(dh);
        float gx = pcx + pw * dx;
        float gy = pcy + ph * dy;
        float* bp = boxes + ((size_t)n * NUM_CLASSES + tid) * 4;
        bp[0] = gx - gw * 0.5f;
        bp[1] = gy - gh * 0.5f;
        bp[2] = gx + gw * 0.5f;
        bp[3] = gy + gh * 0.5f;
    }
}

// ---------------- per-class NMS (80 blocks) ----------------
__global__ void nms_kernel(const float* __restrict__ scores80,
                           const float* __restrict__ boxesAll,
                           float* __restrict__ sortedBoxes,
                           float* __restrict__ sflat) {
    const int c = blockIdx.x;
    const int tid = threadIdx.x;
    const int NT = 256;

    __shared__ float skey[1024];
    __shared__ int sidx[1024];
    __shared__ float4 sbox[N_PROP];
    __shared__ float sarea[N_PROP];
    __shared__ unsigned char keep[N_PROP];

    for (int j = tid; j < 1024; j += NT) {
        skey[j] = (j < N_PROP) ? scores80[j * NUM_CLASSES + c] : -FLT_MAX;
        sidx[j] = j;
    }

    for (int k = 2; k <= 1024; k <<= 1) {
        for (int j = k >> 1; j > 0; j >>= 1) {
            __syncthreads();
            for (int i = tid; i < 1024; i += NT) {
                int ixj = i ^ j;
                if (ixj > i) {
                    float si = skey[i], sx = skey[ixj];
                    int ii = sidx[i], ix = sidx[ixj];
                    bool x_first = (sx > si) || (sx == si && ix < ii);
                    bool up = ((i & k) == 0);
                    if (up ? x_first : !x_first) {
                        skey[i] = sx; skey[ixj] = si;
                        sidx[i] = ix; sidx[ixj] = ii;
                    }
                }
            }
        }
    }
    __syncthreads();

    for (int j = tid; j < N_PROP; j += NT) {
        int oi = sidx[j];
        float4 b = *(const float4*)&boxesAll[((size_t)oi * NUM_CLASSES + c) * 4];
        sbox[j] = b;
        sarea[j] = fmaxf(b.z - b.x, 0.0f) * fmaxf(b.w - b.y, 0.0f);
        keep[j] = (skey[j] > SCORE_THR) ? 1 : 0;
    }
    __syncthreads();

    for (int i = 0; i < N_PROP; i++) {
        if (skey[i] <= SCORE_THR) break;   // uniform read of shared
        __syncthreads();
        if (keep[i]) {
            float4 bi = sbox[i];
            float ai = sarea[i];
            for (int j = i + 1 + tid; j < N_PROP; j += NT) {
                if (!keep[j]) continue;
                float4 bj = sbox[j];
                float iw = fmaxf(fminf(bi.z, bj.z) - fmaxf(bi.x, bj.x), 0.0f);
                float ih = fmaxf(fminf(bi.w, bj.w) - fmaxf(bi.y, bj.y), 0.0f);
                float inter = iw * ih;
                float iou = inter / fmaxf(ai + sarea[j] - inter, 1e-8f);
                if (iou > IOU_THR) keep[j] = 0;
            }
        }
    }
    __syncthreads();

    for (int j = tid; j < N_PROP; j += NT) {
        sflat[c * N_PROP + j] = keep[j] ? skey[j] : -1.0f;
        *(float4*)&sortedBoxes[((size_t)c * N_PROP + j) * 4] = sbox[j];
    }
}

// ---------------- candidate compaction ----------------
__global__ void reset_kernel() { g_ncand = 0; }

__global__ void compact_kernel(const float* __restrict__ sflat) {
    const int tot = NUM_CLASSES * N_PROP;
    for (int i = blockIdx.x * blockDim.x + threadIdx.x; i < tot;
         i += gridDim.x * blockDim.x) {
        float v = sflat[i];
        if (v > 0.0f) {
            int p = atomicAdd(&g_ncand, 1);
            g_cand_v[p] = v;
            g_cand_i[p] = i;
        }
    }
}

// ---------------- top-k + output assembly (1 block) ----------------
__global__ void topk_kernel(const float* __restrict__ sortedBoxes,
                            float* __restrict__ out, int out_size) {
    const int tid = threadIdx.x;
    const int NT = 256;
    const int nc = g_ncand;

    __shared__ float rv[NT];
    __shared__ int ri[NT];
    __shared__ int rs[NT];
    __shared__ float topv[MAX_DET];
    __shared__ int topi[MAX_DET];

    for (int sel = 0; sel < MAX_DET; sel++) {
        float bv = -FLT_MAX;
        int bi = 0x7fffffff, bs = -1;
        for (int j = tid; j < nc; j += NT) {
            float v = g_cand_v[j];
            int fi = g_cand_i[j];
            if (v > bv || (v == bv && fi < bi)) { bv = v; bi = fi; bs = j; }
        }
        rv[tid] = bv; ri[tid] = bi; rs[tid] = bs;
        __syncthreads();
        for (int s = NT / 2; s > 0; s >>= 1) {
            if (tid < s) {
                if (rv[tid + s] > rv[tid] ||
                    (rv[tid + s] == rv[tid] && ri[tid + s] < ri[tid])) {
                    rv[tid] = rv[tid + s]; ri[tid] = ri[tid + s]; rs[tid] = rs[tid + s];
                }
            }
            __syncthreads();
        }
        if (tid == 0) {
            topv[sel] = rv[0];
            topi[sel] = ri[0];
            if (rs[0] >= 0) g_cand_v[rs[0]] = -FLT_MAX;
        }
        __syncthreads();
    }

    if (tid == 0) {
        int nd = 0;
        for (int k = 0; k < MAX_DET; k++)
            if (topv[k] > 0.0f) nd++;
        if (out_size > 0) out[0] = (float)nd;
    }
    __syncthreads();

    for (int k = tid; k < MAX_DET; k += NT) {
        bool valid = topv[k] > 0.0f;
        int oi = topi[k];
        float b0 = 0.f, b1 = 0.f, b2 = 0.f, b3 = 0.f;
        if (valid) {
            const float* bp = &sortedBoxes[(size_t)oi * 4];
            b0 = bp[0]; b1 = bp[1]; b2 = bp[2]; b3 = bp[3];
        }
        if (1 + k * 4 + 3 < out_size) {
            out[1 + k * 4 + 0] = b0;
            out[1 + k * 4 + 1] = b1;
            out[1 + k * 4 + 2] = b2;
            out[1 + k * 4 + 3] = b3;
        }
        if (401 + k < out_size) out[401 + k] = valid ? topv[k] : 0.0f;
        if (501 + k < out_size) out[501 + k] = valid ? (float)(oi / N_PROP) : -1.0f;
    }
    for (int i = 601 + tid; i < out_size; i += NT) out[i] = 0.0f;
}

// ---------------- launch ----------------
extern "C" void kernel_launch(void* const* d_in, const int* in_sizes, int n_in,
                              void* d_out, int out_size) {
    const float* f0 = (const float*)d_in[0];
    const float* f1 = (const float*)d_in[1];
    const float* f2 = (const float*)d_in[2];
    const float* f3 = (const float*)d_in[3];
    const float* props = (const float*)d_in[4];
    const float* fc1_w = (const float*)d_in[5];
    const float* fc1_b = (const float*)d_in[6];
    const float* fc2_w = (const float*)d_in[7];
    const float* fc2_b = (const float*)d_in[8];
    const float* cls_w = (const float*)d_in[9];
    const float* cls_b = (const float*)d_in[10];
    const float* reg_w = (const float*)d_in[11];
    const float* reg_b = (const float*)d_in[12];
    float* out = (float*)d_out;

    float *f0t, *f1t, *f2t, *f3t, *headb, *head_out;
    float *sc80, *boxes, *sboxes, *sflat;
    __nv_bfloat16 *roi_feats, *h1, *h2, *fc1wb, *fc2wb, *headwb;
    cudaGetSymbolAddress((void**)&f0t, g_f0t);
    cudaGetSymbolAddress((void**)&f1t, g_f1t);
    cudaGetSymbolAddress((void**)&f2t, g_f2t);
    cudaGetSymbolAddress((void**)&f3t, g_f3t);
    cudaGetSymbolAddress((void**)&roi_feats, g_roi_feats);
    cudaGetSymbolAddress((void**)&h1, g_h1);
    cudaGetSymbolAddress((void**)&h2, g_h2);
    cudaGetSymbolAddress((void**)&fc1wb, g_fc1w);
    cudaGetSymbolAddress((void**)&fc2wb, g_fc2w);
    cudaGetSymbolAddress((void**)&headwb, g_headw);
    cudaGetSymbolAddress((void**)&headb, g_headb);
    cudaGetSymbolAddress((void**)&head_out, g_head_out);
    cudaGetSymbolAddress((void**)&sc80, g_scores80);
    cudaGetSymbolAddress((void**)&boxes, g_boxes);
    cudaGetSymbolAddress((void**)&sboxes, g_sorted_boxes);
    cudaGetSymbolAddress((void**)&sflat, g_sflat);

    // feature transposes
    {
        dim3 b(32, 8);
        nchw2nhwc_kernel<<<dim3((200 * 336 + 31) / 32, 8), b>>>(f0, f0t, 200 * 336);
        nchw2nhwc_kernel<<<dim3((100 * 168 + 31) / 32, 8), b>>>(f1, f1t, 100 * 168);
        nchw2nhwc_kernel<<<dim3((50 * 84 + 31) / 32, 8), b>>>(f2, f2t, 50 * 84);
        nchw2nhwc_kernel<<<dim3((25 * 42 + 31) / 32, 8), b>>>(f3, f3t, 25 * 42);
    }

    // weight conversions (overlap-able with roi_align on GPU)
    cvt_bf16_kernel<<<(FC * DFEAT / 4 + 255) / 256, 256>>>(fc1_w, fc1wb, FC * DFEAT / 4);
    cvt_bf16_kernel<<<(FC * FC / 4 + 255) / 256, 256>>>(fc2_w, fc2wb, FC * FC / 4);
    build_head_kernel<<<(NHEAD * FC + 255) / 256, 256>>>(cls_w, reg_w, cls_b, reg_b,
                                                         headwb, headb);

    roi_align_kernel<<<N_PROP, 256>>>(f0t, f1t, f2t, f3t, props, roi_feats);

    // fc1: [1000,12544] x [1024,12544]^T
    gemm_bf16_kernel<<<dim3(FC / 64, (N_PROP + 127) / 128), 256>>>(
        roi_feats, fc1wb, fc1_b, h1, N_PROP, FC, DFEAT, 1, 1);
    // fc2
    gemm_bf16_kernel<<<dim3(FC / 64, (N_PROP + 127) / 128), 256>>>(
        h1, fc2wb, fc2_b, h2, N_PROP, FC, FC, 1, 1);
    // fused cls+reg head
    gemm_bf16_kernel<<<dim3((NHEAD + 63) / 64, (N_PROP + 127) / 128), 256>>>(
        h2, headwb, headb, head_out, N_PROP, NHEAD, FC, 0, 0);

    head_kernel<<<N_PROP, 128>>>(head_out, props, sc80, boxes);
    nms_kernel<<<NUM_CLASSES, 256>>>(sc80, boxes, sboxes, sflat);
    reset_kernel<<<1, 1>>>();
    compact_kernel<<<80, 256>>>(sflat);
    topk_kernel<<<1, 256>>>(sboxes, out, out_size);
}

// round 5
// speedup vs baseline: 6.3952x; 1.5517x over previous
#include <cuda_runtime.h>
#include <cuda_bf16.h>
#include <math.h>
#include <float.h>
#include <stdint.h>

#define NUM_CLASSES 80
#define N_PROP 1000
#define CCH 256
#define ROI 7
#define DFEAT (CCH * ROI * ROI)   // 12544
#define FC 1024
#define NHEAD 401                  // 81 cls + 320 reg
#define SCORE_THR 0.05f
#define IOU_THR 0.5f
#define MAX_DET 100
#define MAX_RATIO 4.135166556742356f  // |log(16/1000)|
#define SPLITK 4

// ---------------- device scratch (no cudaMalloc allowed) ----------------
__device__ __nv_bfloat16 g_f0t[200 * 336 * CCH];   // NHWC bf16 features
__device__ __nv_bfloat16 g_f1t[100 * 168 * CCH];
__device__ __nv_bfloat16 g_f2t[50 * 84 * CCH];
__device__ __nv_bfloat16 g_f3t[25 * 42 * CCH];

__device__ __nv_bfloat16 g_roi_feats[N_PROP * DFEAT];
__device__ __nv_bfloat16 g_h1[N_PROP * FC];
__device__ __nv_bfloat16 g_h2[N_PROP * FC];
__device__ __nv_bfloat16 g_fc1w[FC * DFEAT];
__device__ __nv_bfloat16 g_fc2w[FC * FC];
__device__ __nv_bfloat16 g_headw[NHEAD * FC];
__device__ float g_headb[NHEAD];
__device__ float g_head_out[N_PROP * NHEAD];
__device__ float g_part[SPLITK * N_PROP * FC];     // split-K partials (16.4MB)

__device__ float g_scores80[N_PROP * NUM_CLASSES];
__device__ float g_boxes[N_PROP * NUM_CLASSES * 4];
__device__ float g_sorted_boxes[NUM_CLASSES * N_PROP * 4];
__device__ float g_sflat[NUM_CLASSES * N_PROP];

__device__ int g_ncand;
__device__ float g_cand_v[NUM_CLASSES * N_PROP];
__device__ int   g_cand_i[NUM_CLASSES * N_PROP];

// ---------------- NCHW f32 -> NHWC bf16 transpose ----------------
__global__ void nchw2nhwc_kernel(const float* __restrict__ in,
                                 __nv_bfloat16* __restrict__ out, int HW) {
    __shared__ float t[32][33];
    int hw0 = blockIdx.x * 32;
    int c0 = blockIdx.y * 32;
    int x = hw0 + threadIdx.x;
    #pragma unroll
    for (int i = 0; i < 32; i += 8) {
        int c = c0 + threadIdx.y + i;
        if (x < HW) t[threadIdx.y + i][threadIdx.x] = in[(size_t)c * HW + x];
    }
    __syncthreads();
    int co = c0 + threadIdx.x;
    #pragma unroll
    for (int i = 0; i < 32; i += 8) {
        int xo = hw0 + threadIdx.y + i;
        if (xo < HW)
            out[(size_t)xo * CCH + co] = __float2bfloat16(t[threadIdx.x][threadIdx.y + i]);
    }
}

// ---------------- RoI Align (bf16 NHWC in, bf16 out) ----------------
// 128 threads; thread t handles channels 2t, 2t+1 via bf162 loads
__global__ void roi_align_kernel(const __nv_bfloat16* __restrict__ f0,
                                 const __nv_bfloat16* __restrict__ f1,
                                 const __nv_bfloat16* __restrict__ f2,
                                 const __nv_bfloat16* __restrict__ f3,
                                 const float* __restrict__ props,
                                 __nv_bfloat16* __restrict__ out) {
    const int n = blockIdx.x;
    const int tid = threadIdx.x;

    __shared__ int sx0[14], sx1[14], sy0[14], sy1[14];
    __shared__ float slx[14], sly[14];
    __shared__ int svx[14], svy[14];

    float px1 = props[n * 4 + 0];
    float py1 = props[n * 4 + 1];
    float px2 = props[n * 4 + 2];
    float py2 = props[n * 4 + 3];
    float w = px2 - px1, h = py2 - py1;
    float sz = sqrtf(fmaxf(w * h, 1e-6f));
    int lvl = (int)floorf(log2f(sz / 56.0f + 1e-6f));
    lvl = lvl < 0 ? 0 : (lvl > 3 ? 3 : lvl);

    const __nv_bfloat16* feat;
    int H, W;
    if (lvl == 0) { feat = f0; H = 200; W = 336; }
    else if (lvl == 1) { feat = f1; H = 100; W = 168; }
    else if (lvl == 2) { feat = f2; H = 50; W = 84; }
    else { feat = f3; H = 25; W = 42; }
    float scale = 1.0f / (float)(4 << lvl);

    if (tid < 14) {
        int i = tid;
        float pt = ((float)i + 0.5f) / 14.0f;
        {
            float xs = px1 * scale - 0.5f + pt * (w * scale);
            float fx = floorf(xs);
            int x0 = (int)fx; x0 = x0 < 0 ? 0 : (x0 > W - 1 ? W - 1 : x0);
            int x1i = x0 + 1; x1i = x1i > W - 1 ? W - 1 : x1i;
            sx0[i] = x0; sx1[i] = x1i;
            slx[i] = xs - fx;
            svx[i] = (xs >= -1.0f && xs <= (float)W) ? 1 : 0;
        }
        {
            float ys = py1 * scale - 0.5f + pt * (h * scale);
            float fy = floorf(ys);
            int y0 = (int)fy; y0 = y0 < 0 ? 0 : (y0 > H - 1 ? H - 1 : y0);
            int y1i = y0 + 1; y1i = y1i > H - 1 ? H - 1 : y1i;
            sy0[i] = y0; sy1[i] = y1i;
            sly[i] = ys - fy;
            svy[i] = (ys >= -1.0f && ys <= (float)H) ? 1 : 0;
        }
    }
    __syncthreads();

    const __nv_bfloat162* feat2 = (const __nv_bfloat162*)feat;  // [HW][128]
    __nv_bfloat16* op0 = out + (size_t)n * DFEAT + (size_t)(2 * tid) * (ROI * ROI);
    __nv_bfloat16* op1 = op0 + (ROI * ROI);

    #pragma unroll
    for (int py = 0; py < ROI; py++) {
        #pragma unroll
        for (int px = 0; px < ROI; px++) {
            float acc0 = 0.0f, acc1 = 0.0f;
            #pragma unroll
            for (int sy = 0; sy < 2; sy++) {
                int iy = py * 2 + sy;
                int y0 = sy0[iy], y1v = sy1[iy];
                float ly = sly[iy];
                int vy = svy[iy];
                #pragma unroll
                for (int sxs = 0; sxs < 2; sxs++) {
                    int ix = px * 2 + sxs;
                    if (vy && svx[ix]) {
                        int x0 = sx0[ix], x1v = sx1[ix];
                        float lx = slx[ix];
                        float2 v00 = __bfloat1622float2(feat2[((size_t)(y0 * W + x0) << 7) + tid]);
                        float2 v01 = __bfloat1622float2(feat2[((size_t)(y0 * W + x1v) << 7) + tid]);
                        float2 v10 = __bfloat1622float2(feat2[((size_t)(y1v * W + x0) << 7) + tid]);
                        float2 v11 = __bfloat1622float2(feat2[((size_t)(y1v * W + x1v) << 7) + tid]);
                        float wy0 = 1.0f - ly, wx0 = 1.0f - lx;
                        acc0 += wy0 * (wx0 * v00.x + lx * v01.x) + ly * (wx0 * v10.x + lx * v11.x);
                        acc1 += wy0 * (wx0 * v00.y + lx * v01.y) + ly * (wx0 * v10.y + lx * v11.y);
                    }
                }
            }
            op0[py * ROI + px] = __float2bfloat16(acc0 * 0.25f);
            op1[py * ROI + px] = __float2bfloat16(acc1 * 0.25f);
        }
    }
}

// ---------------- weight conversions ----------------
__global__ void cvt_bf16_kernel(const float* __restrict__ s,
                                __nv_bfloat16* __restrict__ d, int n4) {
    int i = blockIdx.x * blockDim.x + threadIdx.x;
    if (i < n4) {
        float4 v = ((const float4*)s)[i];
        ((__nv_bfloat162*)d)[2 * i] = __floats2bfloat162_rn(v.x, v.y);
        ((__nv_bfloat162*)d)[2 * i + 1] = __floats2bfloat162_rn(v.z, v.w);
    }
}

__global__ void build_head_kernel(const float* __restrict__ cls_w,
                                  const float* __restrict__ reg_w,
                                  const float* __restrict__ cls_b,
                                  const float* __restrict__ reg_b,
                                  __nv_bfloat16* __restrict__ wout,
                                  float* __restrict__ bout) {
    int i = blockIdx.x * blockDim.x + threadIdx.x;
    const int total = NHEAD * FC;
    if (i < total) {
        int r = i >> 10, k = i & 1023;
        float v = (r < 81) ? cls_w[r * FC + k] : reg_w[(r - 81) * FC + k];
        wout[i] = __float2bfloat16(v);
    }
    if (i < NHEAD) bout[i] = (i < 81) ? cls_b[i] : reg_b[i - 81];
}

// ---------------- bf16 tensor-core GEMM, split-K partials ----------------
// C_part[z][M,N] = A[M, z*Kc : (z+1)*Kc] @ B[N, same]^T  (fp32 out, no bias)
__device__ __forceinline__ void mma16816(float* c, const uint32_t* a, const uint32_t* b) {
    asm volatile(
        "mma.sync.aligned.m16n8k16.row.col.f32.bf16.bf16.f32 "
        "{%0,%1,%2,%3},{%4,%5,%6,%7},{%8,%9},{%0,%1,%2,%3};"
        : "+f"(c[0]), "+f"(c[1]), "+f"(c[2]), "+f"(c[3])
        : "r"(a[0]), "r"(a[1]), "r"(a[2]), "r"(a[3]), "r"(b[0]), "r"(b[1]));
}

__global__ __launch_bounds__(256, 2)
void gemm_bf16_splitk_kernel(const __nv_bfloat16* __restrict__ Afull,
                             const __nv_bfloat16* __restrict__ Bfull,
                             float* __restrict__ Cpart,
                             int M, int N, int Kc, int lda) {
    const int BM = 128, BN = 64, BK = 32;
    __shared__ __nv_bfloat16 As[128][40];
    __shared__ __nv_bfloat16 Bs[64][40];

    const int tid = threadIdx.x;
    const int warp = tid >> 5, lane = tid & 31;
    const int wm = warp >> 1, wn = warp & 1;
    const int g = lane >> 2, tg = lane & 3;
    const int m0 = blockIdx.y * BM, n0 = blockIdx.x * BN;
    const int z = blockIdx.z;

    const __nv_bfloat16* A = Afull + (size_t)z * Kc;
    const __nv_bfloat16* B = Bfull + (size_t)z * Kc;

    const int aRow = tid >> 2;
    const int kc = (tid & 3) * 8;

    float acc[2][4][4];
    #pragma unroll
    for (int i = 0; i < 2; i++)
        #pragma unroll
        for (int j = 0; j < 4; j++)
            #pragma unroll
            for (int q = 0; q < 4; q++) acc[i][j][q] = 0.0f;

    const uint4 z4 = make_uint4(0u, 0u, 0u, 0u);
    uint4 pa[2], pb;
    {
        int r0 = m0 + aRow, r1 = m0 + aRow + 64;
        pa[0] = (r0 < M) ? *(const uint4*)&A[(size_t)r0 * lda + kc] : z4;
        pa[1] = (r1 < M) ? *(const uint4*)&A[(size_t)r1 * lda + kc] : z4;
        int br = n0 + aRow;
        pb = (br < N && aRow < 64) ? *(const uint4*)&B[(size_t)br * lda + kc] : z4;
    }

    for (int k0 = 0; k0 < Kc; k0 += BK) {
        *(uint4*)&As[aRow][kc] = pa[0];
        *(uint4*)&As[aRow + 64][kc] = pa[1];
        if (aRow < 64) *(uint4*)&Bs[aRow][kc] = pb;
        __syncthreads();

        int kn = k0 + BK;
        if (kn < Kc) {
            int r0 = m0 + aRow, r1 = m0 + aRow + 64;
            pa[0] = (r0 < M) ? *(const uint4*)&A[(size_t)r0 * lda + kn + kc] : z4;
            pa[1] = (r1 < M) ? *(const uint4*)&A[(size_t)r1 * lda + kn + kc] : z4;
            int br = n0 + aRow;
            pb = (br < N && aRow < 64) ? *(const uint4*)&B[(size_t)br * lda + kn + kc] : z4;
        }

        #pragma unroll
        for (int ks = 0; ks < 2; ks++) {
            const int kb = ks * 16;
            uint32_t af[2][4], bf[4][2];
            #pragma unroll
            for (int mt = 0; mt < 2; mt++) {
                int row = wm * 32 + mt * 16;
                af[mt][0] = *(const uint32_t*)&As[row + g][kb + tg * 2];
                af[mt][1] = *(const uint32_t*)&As[row + g + 8][kb + tg * 2];
                af[mt][2] = *(const uint32_t*)&As[row + g][kb + tg * 2 + 8];
                af[mt][3] = *(const uint32_t*)&As[row + g + 8][kb + tg * 2 + 8];
            }
            #pragma unroll
            for (int nt = 0; nt < 4; nt++) {
                int col = wn * 32 + nt * 8 + g;
                bf[nt][0] = *(const uint32_t*)&Bs[col][kb + tg * 2];
                bf[nt][1] = *(const uint32_t*)&Bs[col][kb + tg * 2 + 8];
            }
            #pragma unroll
            for (int mt = 0; mt < 2; mt++)
                #pragma unroll
                for (int nt = 0; nt < 4; nt++)
                    mma16816(acc[mt][nt], af[mt], bf[nt]);
        }
        __syncthreads();
    }

    float* Cp = Cpart + (size_t)z * M * N;
    #pragma unroll
    for (int mt = 0; mt < 2; mt++) {
        #pragma unroll
        for (int nt = 0; nt < 4; nt++) {
            int n = n0 + wn * 32 + nt * 8 + tg * 2;
            if (n >= N) continue;
            #pragma unroll
            for (int rh = 0; rh < 2; rh++) {
                int m = m0 + wm * 32 + mt * 16 + g + rh * 8;
                if (m >= M) continue;
                Cp[(size_t)m * N + n] = acc[mt][nt][rh * 2 + 0];
                if (n + 1 < N) Cp[(size_t)m * N + n + 1] = acc[mt][nt][rh * 2 + 1];
            }
        }
    }
}

// ---------------- split-K reduce + bias (+relu) (+bf16 cvt) ----------------
__global__ void reduce_k_kernel(const float* __restrict__ part,
                                const float* __restrict__ bias,
                                void* __restrict__ out,
                                int M, int N, int relu, int out_bf16) {
    int i = blockIdx.x * blockDim.x + threadIdx.x;
    int tot = M * N;
    if (i >= tot) return;
    int n = i % N;
    float v = part[i];
    #pragma unroll
    for (int s = 1; s < SPLITK; s++) v += part[(size_t)s * tot + i];
    v += bias[n];
    if (relu) v = fmaxf(v, 0.0f);
    if (out_bf16) ((__nv_bfloat16*)out)[i] = __float2bfloat16(v);
    else ((float*)out)[i] = v;
}

// ---------------- softmax + delta2bbox ----------------
__global__ void head_kernel(const float* __restrict__ head_out,
                            const float* __restrict__ props,
                            float* __restrict__ scores80,
                            float* __restrict__ boxes) {
    const int n = blockIdx.x;
    const int tid = threadIdx.x;
    __shared__ float sv[81];
    __shared__ float red[128];

    const float* row = head_out + (size_t)n * NHEAD;
    float v = (tid < 81) ? row[tid] : -FLT_MAX;
    if (tid < 81) sv[tid] = v;
    red[tid] = v;
    __syncthreads();
    for (int s = 64; s > 0; s >>= 1) {
        if (tid < s) red[tid] = fmaxf(red[tid], red[tid + s]);
        __syncthreads();
    }
    float mx = red[0];
    __syncthreads();
    float e = (tid < 81) ? expf(sv[tid] - mx) : 0.0f;
    red[tid] = e;
    __syncthreads();
    for (int s = 64; s > 0; s >>= 1) {
        if (tid < s) red[tid] += red[tid + s];
        __syncthreads();
    }
    float sum = red[0];

    if (tid < NUM_CLASSES) {
        scores80[n * NUM_CLASSES + tid] = e / sum;

        const float* rp = row + 81 + tid * 4;
        float dx = rp[0] * 0.1f;
        float dy = rp[1] * 0.1f;
        float dw = fminf(fmaxf(rp[2] * 0.2f, -MAX_RATIO), MAX_RATIO);
        float dh = fminf(fmaxf(rp[3] * 0.2f, -MAX_RATIO), MAX_RATIO);
        float p0 = props[n * 4 + 0], p1 = props[n * 4 + 1];
        float p2 = props[n * 4 + 2], p3 = props[n * 4 + 3];
        float pcx = (p0 + p2) * 0.5f;
        float pcy = (p1 + p3) * 0.5f;
        float pw = p2 - p0, ph = p3 - p1;
        float gw = pw * expf(dw);
        float gh = ph * expf(dh);
        float gx = pcx + pw * dx;
        float gy = pcy + ph * dy;
        float* bp = boxes + ((size_t)n * NUM_CLASSES + tid) * 4;
        bp[0] = gx - gw * 0.5f;
        bp[1] = gy - gh * 0.5f;
        bp[2] = gx + gw * 0.5f;
        bp[3] = gy + gh * 0.5f;
    }
}

// ---------------- per-class NMS (80 blocks) with empty fast path ----------
__global__ void nms_kernel(const float* __restrict__ scores80,
                           const float* __restrict__ boxesAll,
                           float* __restrict__ sortedBoxes,
                           float* __restrict__ sflat) {
    const int c = blockIdx.x;
    const int tid = threadIdx.x;
    const int NT = 256;

    __shared__ float skey[1024];
    __shared__ int sidx[1024];
    __shared__ float4 sbox[N_PROP];
    __shared__ float sarea[N_PROP];
    __shared__ unsigned char keep[N_PROP];
    __shared__ float redmax[NT];

    // fast path: class max <= threshold -> nothing survives
    float mv = -FLT_MAX;
    for (int j = tid; j < N_PROP; j += NT) {
        float s = scores80[j * NUM_CLASSES + c];
        mv = fmaxf(mv, s);
        skey[j] = s;      // stash for potential full path
    }
    redmax[tid] = mv;
    __syncthreads();
    for (int s = NT / 2; s > 0; s >>= 1) {
        if (tid < s) redmax[tid] = fmaxf(redmax[tid], redmax[tid + s]);
        __syncthreads();
    }
    if (redmax[0] <= SCORE_THR) {
        for (int j = tid; j < N_PROP; j += NT)
            sflat[c * N_PROP + j] = -1.0f;
        return;
    }

    // full path
    for (int j = tid; j < 1024; j += NT) {
        if (j >= N_PROP) skey[j] = -FLT_MAX;
        sidx[j] = j;
    }

    for (int k = 2; k <= 1024; k <<= 1) {
        for (int j = k >> 1; j > 0; j >>= 1) {
            __syncthreads();
            for (int i = tid; i < 1024; i += NT) {
                int ixj = i ^ j;
                if (ixj > i) {
                    float si = skey[i], sx = skey[ixj];
                    int ii = sidx[i], ix = sidx[ixj];
                    bool x_first = (sx > si) || (sx == si && ix < ii);
                    bool up = ((i & k) == 0);
                    if (up ? x_first : !x_first) {
                        skey[i] = sx; skey[ixj] = si;
                        sidx[i] = ix; sidx[ixj] = ii;
                    }
                }
            }
        }
    }
    __syncthreads();

    for (int j = tid; j < N_PROP; j += NT) {
        int oi = sidx[j];
        float4 b = *(const float4*)&boxesAll[((size_t)oi * NUM_CLASSES + c) * 4];
        sbox[j] = b;
        sarea[j] = fmaxf(b.z - b.x, 0.0f) * fmaxf(b.w - b.y, 0.0f);
        keep[j] = (skey[j] > SCORE_THR) ? 1 : 0;
    }
    __syncthreads();

    for (int i = 0; i < N_PROP; i++) {
        if (skey[i] <= SCORE_THR) break;
        __syncthreads();
        if (keep[i]) {
            float4 bi = sbox[i];
            float ai = sarea[i];
            for (int j = i + 1 + tid; j < N_PROP; j += NT) {
                if (!keep[j]) continue;
                float4 bj = sbox[j];
                float iw = fmaxf(fminf(bi.z, bj.z) - fmaxf(bi.x, bj.x), 0.0f);
                float ih = fmaxf(fminf(bi.w, bj.w) - fmaxf(bi.y, bj.y), 0.0f);
                float inter = iw * ih;
                float iou = inter / fmaxf(ai + sarea[j] - inter, 1e-8f);
                if (iou > IOU_THR) keep[j] = 0;
            }
        }
    }
    __syncthreads();

    for (int j = tid; j < N_PROP; j += NT) {
        sflat[c * N_PROP + j] = keep[j] ? skey[j] : -1.0f;
        *(float4*)&sortedBoxes[((size_t)c * N_PROP + j) * 4] = sbox[j];
    }
}

// ---------------- candidate compaction ----------------
__global__ void reset_kernel() { g_ncand = 0; }

__global__ void compact_kernel(const float* __restrict__ sflat) {
    const int tot = NUM_CLASSES * N_PROP;
    for (int i = blockIdx.x * blockDim.x + threadIdx.x; i < tot;
         i += gridDim.x * blockDim.x) {
        float v = sflat[i];
        if (v > 0.0f) {
            int p = atomicAdd(&g_ncand, 1);
            g_cand_v[p] = v;
            g_cand_i[p] = i;
        }
    }
}

// ---------------- top-k + output assembly (1 block) ----------------
__global__ void topk_kernel(const float* __restrict__ sortedBoxes,
                            float* __restrict__ out, int out_size) {
    const int tid = threadIdx.x;
    const int NT = 256;
    const int nc = g_ncand;
    const int nsel = nc < MAX_DET ? nc : MAX_DET;

    __shared__ float rv[NT];
    __shared__ int ri[NT];
    __shared__ int rs[NT];
    __shared__ float topv[MAX_DET];
    __shared__ int topi[MAX_DET];

    for (int k = tid; k < MAX_DET; k += NT) { topv[k] = -FLT_MAX; topi[k] = 0; }
    __syncthreads();

    for (int sel = 0; sel < nsel; sel++) {
        float bv = -FLT_MAX;
        int bi = 0x7fffffff, bs = -1;
        for (int j = tid; j < nc; j += NT) {
            float v = g_cand_v[j];
            int fi = g_cand_i[j];
            if (v > bv || (v == bv && fi < bi)) { bv = v; bi = fi; bs = j; }
        }
        rv[tid] = bv; ri[tid] = bi; rs[tid] = bs;
        __syncthreads();
        for (int s = NT / 2; s > 0; s >>= 1) {
            if (tid < s) {
                if (rv[tid + s] > rv[tid] ||
                    (rv[tid + s] == rv[tid] && ri[tid + s] < ri[tid])) {
                    rv[tid] = rv[tid + s]; ri[tid] = ri[tid + s]; rs[tid] = rs[tid + s];
                }
            }
            __syncthreads();
        }
        if (tid == 0) {
            topv[sel] = rv[0];
            topi[sel] = ri[0];
            if (rs[0] >= 0) g_cand_v[rs[0]] = -FLT_MAX;
        }
        __syncthreads();
    }

    if (tid == 0) {
        int nd = 0;
        for (int k = 0; k < MAX_DET; k++)
            if (topv[k] > 0.0f) nd++;
        if (out_size > 0) out[0] = (float)nd;
    }
    __syncthreads();

    for (int k = tid; k < MAX_DET; k += NT) {
        bool valid = topv[k] > 0.0f;
        int oi = topi[k];
        float b0 = 0.f, b1 = 0.f, b2 = 0.f, b3 = 0.f;
        if (valid) {
            const float* bp = &sortedBoxes[(size_t)oi * 4];
            b0 = bp[0]; b1 = bp[1]; b2 = bp[2]; b3 = bp[3];
        }
        if (1 + k * 4 + 3 < out_size) {
            out[1 + k * 4 + 0] = b0;
            out[1 + k * 4 + 1] = b1;
            out[1 + k * 4 + 2] = b2;
            out[1 + k * 4 + 3] = b3;
        }
        if (401 + k < out_size) out[401 + k] = valid ? topv[k] : 0.0f;
        if (501 + k < out_size) out[501 + k] = valid ? (float)(oi / N_PROP) : -1.0f;
    }
    for (int i = 601 + tid; i < out_size; i += NT) out[i] = 0.0f;
}

// ---------------- launch ----------------
extern "C" void kernel_launch(void* const* d_in, const int* in_sizes, int n_in,
                              void* d_out, int out_size) {
    const float* f0 = (const float*)d_in[0];
    const float* f1 = (const float*)d_in[1];
    const float* f2 = (const float*)d_in[2];
    const float* f3 = (const float*)d_in[3];
    const float* props = (const float*)d_in[4];
    const float* fc1_w = (const float*)d_in[5];
    const float* fc1_b = (const float*)d_in[6];
    const float* fc2_w = (const float*)d_in[7];
    const float* fc2_b = (const float*)d_in[8];
    const float* cls_w = (const float*)d_in[9];
    const float* cls_b = (const float*)d_in[10];
    const float* reg_w = (const float*)d_in[11];
    const float* reg_b = (const float*)d_in[12];
    float* out = (float*)d_out;

    __nv_bfloat16 *f0t, *f1t, *f2t, *f3t;
    __nv_bfloat16 *roi_feats, *h1, *h2, *fc1wb, *fc2wb, *headwb;
    float *headb, *head_out, *part;
    float *sc80, *boxes, *sboxes, *sflat;
    cudaGetSymbolAddress((void**)&f0t, g_f0t);
    cudaGetSymbolAddress((void**)&f1t, g_f1t);
    cudaGetSymbolAddress((void**)&f2t, g_f2t);
    cudaGetSymbolAddress((void**)&f3t, g_f3t);
    cudaGetSymbolAddress((void**)&roi_feats, g_roi_feats);
    cudaGetSymbolAddress((void**)&h1, g_h1);
    cudaGetSymbolAddress((void**)&h2, g_h2);
    cudaGetSymbolAddress((void**)&fc1wb, g_fc1w);
    cudaGetSymbolAddress((void**)&fc2wb, g_fc2w);
    cudaGetSymbolAddress((void**)&headwb, g_headw);
    cudaGetSymbolAddress((void**)&headb, g_headb);
    cudaGetSymbolAddress((void**)&head_out, g_head_out);
    cudaGetSymbolAddress((void**)&part, g_part);
    cudaGetSymbolAddress((void**)&sc80, g_scores80);
    cudaGetSymbolAddress((void**)&boxes, g_boxes);
    cudaGetSymbolAddress((void**)&sboxes, g_sorted_boxes);
    cudaGetSymbolAddress((void**)&sflat, g_sflat);

    {
        dim3 b(32, 8);
        nchw2nhwc_kernel<<<dim3((200 * 336 + 31) / 32, 8), b>>>(f0, f0t, 200 * 336);
        nchw2nhwc_kernel<<<dim3((100 * 168 + 31) / 32, 8), b>>>(f1, f1t, 100 * 168);
        nchw2nhwc_kernel<<<dim3((50 * 84 + 31) / 32, 8), b>>>(f2, f2t, 50 * 84);
        nchw2nhwc_kernel<<<dim3((25 * 42 + 31) / 32, 8), b>>>(f3, f3t, 25 * 42);
    }

    cvt_bf16_kernel<<<(FC * DFEAT / 4 + 255) / 256, 256>>>(fc1_w, fc1wb, FC * DFEAT / 4);
    cvt_bf16_kernel<<<(FC * FC / 4 + 255) / 256, 256>>>(fc2_w, fc2wb, FC * FC / 4);
    build_head_kernel<<<(NHEAD * FC + 255) / 256, 256>>>(cls_w, reg_w, cls_b, reg_b,
                                                         headwb, headb);

    roi_align_kernel<<<N_PROP, 128>>>(f0t, f1t, f2t, f3t, props, roi_feats);

    // fc1: K=12544, Kc=3136
    gemm_bf16_splitk_kernel<<<dim3(FC / 64, (N_PROP + 127) / 128, SPLITK), 256>>>(
        roi_feats, fc1wb, part, N_PROP, FC, DFEAT / SPLITK, DFEAT);
    reduce_k_kernel<<<(N_PROP * FC + 255) / 256, 256>>>(part, fc1_b, h1, N_PROP, FC, 1, 1);

    // fc2: K=1024, Kc=256
    gemm_bf16_splitk_kernel<<<dim3(FC / 64, (N_PROP + 127) / 128, SPLITK), 256>>>(
        h1, fc2wb, part, N_PROP, FC, FC / SPLITK, FC);
    reduce_k_kernel<<<(N_PROP * FC + 255) / 256, 256>>>(part, fc2_b, h2, N_PROP, FC, 1, 1);

    // head: N=401, K=1024, Kc=256
    gemm_bf16_splitk_kernel<<<dim3((NHEAD + 63) / 64, (N_PROP + 127) / 128, SPLITK), 256>>>(
        h2, headwb, part, N_PROP, NHEAD, FC / SPLITK, FC);
    reduce_k_kernel<<<(N_PROP * NHEAD + 255) / 256, 256>>>(part, headb, head_out,
                                                           N_PROP, NHEAD, 0, 0);

    head_kernel<<<N_PROP, 128>>>(head_out, props, sc80, boxes);
    nms_kernel<<<NUM_CLASSES, 256>>>(sc80, boxes, sboxes, sflat);
    reset_kernel<<<1, 1>>>();
    compact_kernel<<<80, 256>>>(sflat);
    topk_kernel<<<1, 256>>>(sboxes, out, out_size);
}

// round 6
// speedup vs baseline: 6.6415x; 1.0385x over previous
#include <cuda_runtime.h>
#include <cuda_bf16.h>
#include <math.h>
#include <float.h>
#include <stdint.h>

#define NUM_CLASSES 80
#define N_PROP 1000
#define CCH 256
#define ROI 7
#define DFEAT (CCH * ROI * ROI)   // 12544
#define FC 1024
#define NHEAD 401                  // 81 cls + 320 reg
#define SCORE_THR 0.05f
#define IOU_THR 0.5f
#define MAX_DET 100
#define MAX_RATIO 4.135166556742356f
#define SPLITK 4

// ---------------- device scratch ----------------
__device__ __nv_bfloat16 g_f0t[200 * 336 * CCH];
__device__ __nv_bfloat16 g_f1t[100 * 168 * CCH];
__device__ __nv_bfloat16 g_f2t[50 * 84 * CCH];
__device__ __nv_bfloat16 g_f3t[25 * 42 * CCH];

__device__ __nv_bfloat16 g_roi_feats[N_PROP * DFEAT];
__device__ __nv_bfloat16 g_h1[N_PROP * FC];
__device__ __nv_bfloat16 g_h2[N_PROP * FC];
__device__ float g_headw[NHEAD * FC];     // concatenated f32 head weights
__device__ float g_headb[NHEAD];
__device__ float g_head_out[N_PROP * NHEAD];
__device__ float g_part[SPLITK * N_PROP * FC];

__device__ float g_scores80[N_PROP * NUM_CLASSES];
__device__ float g_boxes[N_PROP * NUM_CLASSES * 4];
__device__ float g_sorted_boxes[NUM_CLASSES * N_PROP * 4];
__device__ float g_sflat[NUM_CLASSES * N_PROP];

__device__ int g_ncand;
__device__ float g_cand_v[NUM_CLASSES * N_PROP];
__device__ int   g_cand_i[NUM_CLASSES * N_PROP];

// ---------------- fused NCHW f32 -> NHWC bf16 transpose (all 4 levels) -----
// tile offsets per level in units of 32-wide HW tiles:
//  L0: HW=67200 -> 2100 tiles, L1: 16800 -> 525, L2: 4200 -> 132, L3: 1050 -> 33
__global__ void nchw2nhwc_all_kernel(const float* __restrict__ f0,
                                     const float* __restrict__ f1,
                                     const float* __restrict__ f2,
                                     const float* __restrict__ f3,
                                     __nv_bfloat16* __restrict__ o0,
                                     __nv_bfloat16* __restrict__ o1,
                                     __nv_bfloat16* __restrict__ o2,
                                     __nv_bfloat16* __restrict__ o3) {
    __shared__ float t[32][33];
    int bt = blockIdx.x;
    const float* in; __nv_bfloat16* out; int HW; int tile;
    if (bt < 2100)      { in = f0; out = o0; HW = 67200; tile = bt; }
    else if (bt < 2625) { in = f1; out = o1; HW = 16800; tile = bt - 2100; }
    else if (bt < 2757) { in = f2; out = o2; HW = 4200;  tile = bt - 2625; }
    else                { in = f3; out = o3; HW = 1050;  tile = bt - 2757; }

    int hw0 = tile * 32;
    int c0 = blockIdx.y * 32;
    int x = hw0 + threadIdx.x;
    #pragma unroll
    for (int i = 0; i < 32; i += 8) {
        int c = c0 + threadIdx.y + i;
        if (x < HW) t[threadIdx.y + i][threadIdx.x] = in[(size_t)c * HW + x];
    }
    __syncthreads();
    int co = c0 + threadIdx.x;
    #pragma unroll
    for (int i = 0; i < 32; i += 8) {
        int xo = hw0 + threadIdx.y + i;
        if (xo < HW)
            out[(size_t)xo * CCH + co] = __float2bfloat16(t[threadIdx.x][threadIdx.y + i]);
    }
}

// ---------------- RoI Align (bf16 NHWC in, bf16 out) ----------------
__global__ void roi_align_kernel(const __nv_bfloat16* __restrict__ f0,
                                 const __nv_bfloat16* __restrict__ f1,
                                 const __nv_bfloat16* __restrict__ f2,
                                 const __nv_bfloat16* __restrict__ f3,
                                 const float* __restrict__ props,
                                 __nv_bfloat16* __restrict__ out) {
    const int n = blockIdx.x;
    const int tid = threadIdx.x;

    __shared__ int sx0[14], sx1[14], sy0[14], sy1[14];
    __shared__ float slx[14], sly[14];
    __shared__ int svx[14], svy[14];

    float px1 = props[n * 4 + 0];
    float py1 = props[n * 4 + 1];
    float px2 = props[n * 4 + 2];
    float py2 = props[n * 4 + 3];
    float w = px2 - px1, h = py2 - py1;
    float sz = sqrtf(fmaxf(w * h, 1e-6f));
    int lvl = (int)floorf(log2f(sz / 56.0f + 1e-6f));
    lvl = lvl < 0 ? 0 : (lvl > 3 ? 3 : lvl);

    const __nv_bfloat16* feat;
    int H, W;
    if (lvl == 0) { feat = f0; H = 200; W = 336; }
    else if (lvl == 1) { feat = f1; H = 100; W = 168; }
    else if (lvl == 2) { feat = f2; H = 50; W = 84; }
    else { feat = f3; H = 25; W = 42; }
    float scale = 1.0f / (float)(4 << lvl);

    if (tid < 14) {
        int i = tid;
        float pt = ((float)i + 0.5f) / 14.0f;
        {
            float xs = px1 * scale - 0.5f + pt * (w * scale);
            float fx = floorf(xs);
            int x0 = (int)fx; x0 = x0 < 0 ? 0 : (x0 > W - 1 ? W - 1 : x0);
            int x1i = x0 + 1; x1i = x1i > W - 1 ? W - 1 : x1i;
            sx0[i] = x0; sx1[i] = x1i;
            slx[i] = xs - fx;
            svx[i] = (xs >= -1.0f && xs <= (float)W) ? 1 : 0;
        }
        {
            float ys = py1 * scale - 0.5f + pt * (h * scale);
            float fy = floorf(ys);
            int y0 = (int)fy; y0 = y0 < 0 ? 0 : (y0 > H - 1 ? H - 1 : y0);
            int y1i = y0 + 1; y1i = y1i > H - 1 ? H - 1 : y1i;
            sy0[i] = y0; sy1[i] = y1i;
            sly[i] = ys - fy;
            svy[i] = (ys >= -1.0f && ys <= (float)H) ? 1 : 0;
        }
    }
    __syncthreads();

    const __nv_bfloat162* feat2 = (const __nv_bfloat162*)feat;
    __nv_bfloat16* op0 = out + (size_t)n * DFEAT + (size_t)(2 * tid) * (ROI * ROI);
    __nv_bfloat16* op1 = op0 + (ROI * ROI);

    #pragma unroll
    for (int py = 0; py < ROI; py++) {
        #pragma unroll
        for (int px = 0; px < ROI; px++) {
            float acc0 = 0.0f, acc1 = 0.0f;
            #pragma unroll
            for (int sy = 0; sy < 2; sy++) {
                int iy = py * 2 + sy;
                int y0 = sy0[iy], y1v = sy1[iy];
                float ly = sly[iy];
                int vy = svy[iy];
                #pragma unroll
                for (int sxs = 0; sxs < 2; sxs++) {
                    int ix = px * 2 + sxs;
                    if (vy && svx[ix]) {
                        int x0 = sx0[ix], x1v = sx1[ix];
                        float lx = slx[ix];
                        float2 v00 = __bfloat1622float2(feat2[((size_t)(y0 * W + x0) << 7) + tid]);
                        float2 v01 = __bfloat1622float2(feat2[((size_t)(y0 * W + x1v) << 7) + tid]);
                        float2 v10 = __bfloat1622float2(feat2[((size_t)(y1v * W + x0) << 7) + tid]);
                        float2 v11 = __bfloat1622float2(feat2[((size_t)(y1v * W + x1v) << 7) + tid]);
                        float wy0 = 1.0f - ly, wx0 = 1.0f - lx;
                        acc0 += wy0 * (wx0 * v00.x + lx * v01.x) + ly * (wx0 * v10.x + lx * v11.x);
                        acc1 += wy0 * (wx0 * v00.y + lx * v01.y) + ly * (wx0 * v10.y + lx * v11.y);
                    }
                }
            }
            op0[py * ROI + px] = __float2bfloat16(acc0 * 0.25f);
            op1[py * ROI + px] = __float2bfloat16(acc1 * 0.25f);
        }
    }
}

// ---------------- head weight concat (f32, small) ----------------
__global__ void build_head_kernel(const float* __restrict__ cls_w,
                                  const float* __restrict__ reg_w,
                                  const float* __restrict__ cls_b,
                                  const float* __restrict__ reg_b,
                                  float* __restrict__ wout,
                                  float* __restrict__ bout) {
    int i = blockIdx.x * blockDim.x + threadIdx.x;
    const int total = NHEAD * FC;
    if (i < total) {
        int r = i >> 10, k = i & 1023;
        wout[i] = (r < 81) ? cls_w[r * FC + k] : reg_w[(r - 81) * FC + k];
    }
    if (i < NHEAD) bout[i] = (i < 81) ? cls_b[i] : reg_b[i - 81];
}

// ---------------- bf16 tensor-core GEMM v2, split-K, B from f32 ------------
// BM=128, BN=128, BK=32, 512 threads = 16 warps (4m x 4n), warp tile 32x32.
// A: bf16 row-major [M, lda]; B: f32 row-major [N, lda] converted inline.
__device__ __forceinline__ void mma16816(float* c, const uint32_t* a, const uint32_t* b) {
    asm volatile(
        "mma.sync.aligned.m16n8k16.row.col.f32.bf16.bf16.f32 "
        "{%0,%1,%2,%3},{%4,%5,%6,%7},{%8,%9},{%0,%1,%2,%3};"
        : "+f"(c[0]), "+f"(c[1]), "+f"(c[2]), "+f"(c[3])
        : "r"(a[0]), "r"(a[1]), "r"(a[2]), "r"(a[3]), "r"(b[0]), "r"(b[1]));
}

__global__ __launch_bounds__(512)
void gemm_bf16_splitk_kernel(const __nv_bfloat16* __restrict__ Afull,
                             const float* __restrict__ Bfull,
                             float* __restrict__ Cpart,
                             int M, int N, int Kc, int lda) {
    const int BK = 32;
    __shared__ __nv_bfloat16 As[128][40];
    __shared__ __nv_bfloat16 Bs[128][40];

    const int tid = threadIdx.x;
    const int warp = tid >> 5, lane = tid & 31;
    const int wm = warp >> 2, wn = warp & 3;      // 4m x 4n
    const int g = lane >> 2, tg = lane & 3;
    const int m0 = blockIdx.y * 128, n0 = blockIdx.x * 128;
    const int z = blockIdx.z;

    const __nv_bfloat16* A = Afull + (size_t)z * Kc;
    const float* B = Bfull + (size_t)z * Kc;

    const int row = tid >> 2;            // 0..127
    const int kc = (tid & 3) * 8;        // 0,8,16,24

    float acc[2][4][4];
    #pragma unroll
    for (int i = 0; i < 2; i++)
        #pragma unroll
        for (int j = 0; j < 4; j++)
            #pragma unroll
            for (int q = 0; q < 4; q++) acc[i][j][q] = 0.0f;

    const uint4 zu4 = make_uint4(0u, 0u, 0u, 0u);
    const float4 zf4 = make_float4(0.f, 0.f, 0.f, 0.f);
    uint4 pa;
    float4 pb0, pb1;
    {
        int ar = m0 + row;
        pa = (ar < M) ? *(const uint4*)&A[(size_t)ar * lda + kc] : zu4;
        int br = n0 + row;
        if (br < N) {
            pb0 = *(const float4*)&B[(size_t)br * lda + kc];
            pb1 = *(const float4*)&B[(size_t)br * lda + kc + 4];
        } else { pb0 = zf4; pb1 = zf4; }
    }

    for (int k0 = 0; k0 < Kc; k0 += BK) {
        *(uint4*)&As[row][kc] = pa;
        {
            __nv_bfloat162* bs2 = (__nv_bfloat162*)&Bs[row][kc];
            bs2[0] = __floats2bfloat162_rn(pb0.x, pb0.y);
            bs2[1] = __floats2bfloat162_rn(pb0.z, pb0.w);
            bs2[2] = __floats2bfloat162_rn(pb1.x, pb1.y);
            bs2[3] = __floats2bfloat162_rn(pb1.z, pb1.w);
        }
        __syncthreads();

        int kn = k0 + BK;
        if (kn < Kc) {
            int ar = m0 + row;
            pa = (ar < M) ? *(const uint4*)&A[(size_t)ar * lda + kn + kc] : zu4;
            int br = n0 + row;
            if (br < N) {
                pb0 = *(const float4*)&B[(size_t)br * lda + kn + kc];
                pb1 = *(const float4*)&B[(size_t)br * lda + kn + kc + 4];
            } else { pb0 = zf4; pb1 = zf4; }
        }

        #pragma unroll
        for (int ks = 0; ks < 2; ks++) {
            const int kb = ks * 16;
            uint32_t af[2][4], bf[4][2];
            #pragma unroll
            for (int mt = 0; mt < 2; mt++) {
                int r = wm * 32 + mt * 16;
                af[mt][0] = *(const uint32_t*)&As[r + g][kb + tg * 2];
                af[mt][1] = *(const uint32_t*)&As[r + g + 8][kb + tg * 2];
                af[mt][2] = *(const uint32_t*)&As[r + g][kb + tg * 2 + 8];
                af[mt][3] = *(const uint32_t*)&As[r + g + 8][kb + tg * 2 + 8];
            }
            #pragma unroll
            for (int nt = 0; nt < 4; nt++) {
                int col = wn * 32 + nt * 8 + g;
                bf[nt][0] = *(const uint32_t*)&Bs[col][kb + tg * 2];
                bf[nt][1] = *(const uint32_t*)&Bs[col][kb + tg * 2 + 8];
            }
            #pragma unroll
            for (int mt = 0; mt < 2; mt++)
                #pragma unroll
                for (int nt = 0; nt < 4; nt++)
                    mma16816(acc[mt][nt], af[mt], bf[nt]);
        }
        __syncthreads();
    }

    float* Cp = Cpart + (size_t)z * M * N;
    #pragma unroll
    for (int mt = 0; mt < 2; mt++) {
        #pragma unroll
        for (int nt = 0; nt < 4; nt++) {
            int n = n0 + wn * 32 + nt * 8 + tg * 2;
            if (n >= N) continue;
            #pragma unroll
            for (int rh = 0; rh < 2; rh++) {
                int m = m0 + wm * 32 + mt * 16 + g + rh * 8;
                if (m >= M) continue;
                Cp[(size_t)m * N + n] = acc[mt][nt][rh * 2 + 0];
                if (n + 1 < N) Cp[(size_t)m * N + n + 1] = acc[mt][nt][rh * 2 + 1];
            }
        }
    }
}

// ---------------- split-K reduce + bias (+relu) (+bf16 cvt) ----------------
__global__ void reduce_k_kernel(const float* __restrict__ part,
                                const float* __restrict__ bias,
                                void* __restrict__ out,
                                int M, int N, int relu, int out_bf16) {
    int i = blockIdx.x * blockDim.x + threadIdx.x;
    int tot = M * N;
    if (i >= tot) return;
    int n = i % N;
    float v = part[i];
    #pragma unroll
    for (int s = 1; s < SPLITK; s++) v += part[(size_t)s * tot + i];
    v += bias[n];
    if (relu) v = fmaxf(v, 0.0f);
    if (out_bf16) ((__nv_bfloat16*)out)[i] = __float2bfloat16(v);
    else ((float*)out)[i] = v;
}

// ---------------- softmax + delta2bbox (also zeroes g_ncand) ---------------
__global__ void head_kernel(const float* __restrict__ head_out,
                            const float* __restrict__ props,
                            float* __restrict__ scores80,
                            float* __restrict__ boxes) {
    const int n = blockIdx.x;
    const int tid = threadIdx.x;
    if (n == 0 && tid == 0) g_ncand = 0;

    __shared__ float sv[81];
    __shared__ float red[128];

    const float* row = head_out + (size_t)n * NHEAD;
    float v = (tid < 81) ? row[tid] : -FLT_MAX;
    if (tid < 81) sv[tid] = v;
    red[tid] = v;
    __syncthreads();
    for (int s = 64; s > 0; s >>= 1) {
        if (tid < s) red[tid] = fmaxf(red[tid], red[tid + s]);
        __syncthreads();
    }
    float mx = red[0];
    __syncthreads();
    float e = (tid < 81) ? expf(sv[tid] - mx) : 0.0f;
    red[tid] = e;
    __syncthreads();
    for (int s = 64; s > 0; s >>= 1) {
        if (tid < s) red[tid] += red[tid + s];
        __syncthreads();
    }
    float sum = red[0];

    if (tid < NUM_CLASSES) {
        scores80[n * NUM_CLASSES + tid] = e / sum;

        const float* rp = row + 81 + tid * 4;
        float dx = rp[0] * 0.1f;
        float dy = rp[1] * 0.1f;
        float dw = fminf(fmaxf(rp[2] * 0.2f, -MAX_RATIO), MAX_RATIO);
        float dh = fminf(fmaxf(rp[3] * 0.2f, -MAX_RATIO), MAX_RATIO);
        float p0 = props[n * 4 + 0], p1 = props[n * 4 + 1];
        float p2 = props[n * 4 + 2], p3 = props[n * 4 + 3];
        float pcx = (p0 + p2) * 0.5f;
        float pcy = (p1 + p3) * 0.5f;
        float pw = p2 - p0, ph = p3 - p1;
        float gw = pw * expf(dw);
        float gh = ph * expf(dh);
        float gx = pcx + pw * dx;
        float gy = pcy + ph * dy;
        float* bp = boxes + ((size_t)n * NUM_CLASSES + tid) * 4;
        bp[0] = gx - gw * 0.5f;
        bp[1] = gy - gh * 0.5f;
        bp[2] = gx + gw * 0.5f;
        bp[3] = gy + gh * 0.5f;
    }
}

// ---------------- per-class NMS (80 blocks) with empty fast path ----------
__global__ void nms_kernel(const float* __restrict__ scores80,
                           const float* __restrict__ boxesAll,
                           float* __restrict__ sortedBoxes,
                           float* __restrict__ sflat) {
    const int c = blockIdx.x;
    const int tid = threadIdx.x;
    const int NT = 256;

    __shared__ float skey[1024];
    __shared__ int sidx[1024];
    __shared__ float4 sbox[N_PROP];
    __shared__ float sarea[N_PROP];
    __shared__ unsigned char keep[N_PROP];
    __shared__ float redmax[NT];

    float mv = -FLT_MAX;
    for (int j = tid; j < N_PROP; j += NT) {
        float s = scores80[j * NUM_CLASSES + c];
        mv = fmaxf(mv, s);
        skey[j] = s;
    }
    redmax[tid] = mv;
    __syncthreads();
    for (int s = NT / 2; s > 0; s >>= 1) {
        if (tid < s) redmax[tid] = fmaxf(redmax[tid], redmax[tid + s]);
        __syncthreads();
    }
    if (redmax[0] <= SCORE_THR) {
        for (int j = tid; j < N_PROP; j += NT)
            sflat[c * N_PROP + j] = -1.0f;
        return;
    }

    for (int j = tid; j < 1024; j += NT) {
        if (j >= N_PROP) skey[j] = -FLT_MAX;
        sidx[j] = j;
    }

    for (int k = 2; k <= 1024; k <<= 1) {
        for (int j = k >> 1; j > 0; j >>= 1) {
            __syncthreads();
            for (int i = tid; i < 1024; i += NT) {
                int ixj = i ^ j;
                if (ixj > i) {
                    float si = skey[i], sx = skey[ixj];
                    int ii = sidx[i], ix = sidx[ixj];
                    bool x_first = (sx > si) || (sx == si && ix < ii);
                    bool up = ((i & k) == 0);
                    if (up ? x_first : !x_first) {
                        skey[i] = sx; skey[ixj] = si;
                        sidx[i] = ix; sidx[ixj] = ii;
                    }
                }
            }
        }
    }
    __syncthreads();

    for (int j = tid; j < N_PROP; j += NT) {
        int oi = sidx[j];
        float4 b = *(const float4*)&boxesAll[((size_t)oi * NUM_CLASSES + c) * 4];
        sbox[j] = b;
        sarea[j] = fmaxf(b.z - b.x, 0.0f) * fmaxf(b.w - b.y, 0.0f);
        keep[j] = (skey[j] > SCORE_THR) ? 1 : 0;
    }
    __syncthreads();

    for (int i = 0; i < N_PROP; i++) {
        if (skey[i] <= SCORE_THR) break;
        __syncthreads();
        if (keep[i]) {
            float4 bi = sbox[i];
            float ai = sarea[i];
            for (int j = i + 1 + tid; j < N_PROP; j += NT) {
                if (!keep[j]) continue;
                float4 bj = sbox[j];
                float iw = fmaxf(fminf(bi.z, bj.z) - fmaxf(bi.x, bj.x), 0.0f);
                float ih = fmaxf(fminf(bi.w, bj.w) - fmaxf(bi.y, bj.y), 0.0f);
                float inter = iw * ih;
                float iou = inter / fmaxf(ai + sarea[j] - inter, 1e-8f);
                if (iou > IOU_THR) keep[j] = 0;
            }
        }
    }
    __syncthreads();

    for (int j = tid; j < N_PROP; j += NT) {
        sflat[c * N_PROP + j] = keep[j] ? skey[j] : -1.0f;
        *(float4*)&sortedBoxes[((size_t)c * N_PROP + j) * 4] = sbox[j];
    }
}

// ---------------- candidate compaction ----------------
__global__ void compact_kernel(const float* __restrict__ sflat) {
    const int tot = NUM_CLASSES * N_PROP;
    for (int i = blockIdx.x * blockDim.x + threadIdx.x; i < tot;
         i += gridDim.x * blockDim.x) {
        float v = sflat[i];
        if (v > 0.0f) {
            int p = atomicAdd(&g_ncand, 1);
            g_cand_v[p] = v;
            g_cand_i[p] = i;
        }
    }
}

// ---------------- top-k + output assembly (1 block) ----------------
__global__ void topk_kernel(const float* __restrict__ sortedBoxes,
                            float* __restrict__ out, int out_size) {
    const int tid = threadIdx.x;
    const int NT = 256;
    const int nc = g_ncand;
    const int nsel = nc < MAX_DET ? nc : MAX_DET;

    __shared__ float rv[NT];
    __shared__ int ri[NT];
    __shared__ int rs[NT];
    __shared__ float topv[MAX_DET];
    __shared__ int topi[MAX_DET];

    for (int k = tid; k < MAX_DET; k += NT) { topv[k] = -FLT_MAX; topi[k] = 0; }
    __syncthreads();

    for (int sel = 0; sel < nsel; sel++) {
        float bv = -FLT_MAX;
        int bi = 0x7fffffff, bs = -1;
        for (int j = tid; j < nc; j += NT) {
            float v = g_cand_v[j];
            int fi = g_cand_i[j];
            if (v > bv || (v == bv && fi < bi)) { bv = v; bi = fi; bs = j; }
        }
        rv[tid] = bv; ri[tid] = bi; rs[tid] = bs;
        __syncthreads();
        for (int s = NT / 2; s > 0; s >>= 1) {
            if (tid < s) {
                if (rv[tid + s] > rv[tid] ||
                    (rv[tid + s] == rv[tid] && ri[tid + s] < ri[tid])) {
                    rv[tid] = rv[tid + s]; ri[tid] = ri[tid + s]; rs[tid] = rs[tid + s];
                }
            }
            __syncthreads();
        }
        if (tid == 0) {
            topv[sel] = rv[0];
            topi[sel] = ri[0];
            if (rs[0] >= 0) g_cand_v[rs[0]] = -FLT_MAX;
        }
        __syncthreads();
    }

    if (tid == 0) {
        int nd = 0;
        for (int k = 0; k < MAX_DET; k++)
            if (topv[k] > 0.0f) nd++;
        if (out_size > 0) out[0] = (float)nd;
    }
    __syncthreads();

    for (int k = tid; k < MAX_DET; k += NT) {
        bool valid = topv[k] > 0.0f;
        int oi = topi[k];
        float b0 = 0.f, b1 = 0.f, b2 = 0.f, b3 = 0.f;
        if (valid) {
            const float* bp = &sortedBoxes[(size_t)oi * 4];
            b0 = bp[0]; b1 = bp[1]; b2 = bp[2]; b3 = bp[3];
        }
        if (1 + k * 4 + 3 < out_size) {
            out[1 + k * 4 + 0] = b0;
            out[1 + k * 4 + 1] = b1;
            out[1 + k * 4 + 2] = b2;
            out[1 + k * 4 + 3] = b3;
        }
        if (401 + k < out_size) out[401 + k] = valid ? topv[k] : 0.0f;
        if (501 + k < out_size) out[501 + k] = valid ? (float)(oi / N_PROP) : -1.0f;
    }
    for (int i = 601 + tid; i < out_size; i += NT) out[i] = 0.0f;
}

// ---------------- launch ----------------
extern "C" void kernel_launch(void* const* d_in, const int* in_sizes, int n_in,
                              void* d_out, int out_size) {
    const float* f0 = (const float*)d_in[0];
    const float* f1 = (const float*)d_in[1];
    const float* f2 = (const float*)d_in[2];
    const float* f3 = (const float*)d_in[3];
    const float* props = (const float*)d_in[4];
    const float* fc1_w = (const float*)d_in[5];
    const float* fc1_b = (const float*)d_in[6];
    const float* fc2_w = (const float*)d_in[7];
    const float* fc2_b = (const float*)d_in[8];
    const float* cls_w = (const float*)d_in[9];
    const float* cls_b = (const float*)d_in[10];
    const float* reg_w = (const float*)d_in[11];
    const float* reg_b = (const float*)d_in[12];
    float* out = (float*)d_out;

    __nv_bfloat16 *f0t, *f1t, *f2t, *f3t, *roi_feats, *h1, *h2;
    float *headw, *headb, *head_out, *part;
    float *sc80, *boxes, *sboxes, *sflat;
    cudaGetSymbolAddress((void**)&f0t, g_f0t);
    cudaGetSymbolAddress((void**)&f1t, g_f1t);
    cudaGetSymbolAddress((void**)&f2t, g_f2t);
    cudaGetSymbolAddress((void**)&f3t, g_f3t);
    cudaGetSymbolAddress((void**)&roi_feats, g_roi_feats);
    cudaGetSymbolAddress((void**)&h1, g_h1);
    cudaGetSymbolAddress((void**)&h2, g_h2);
    cudaGetSymbolAddress((void**)&headw, g_headw);
    cudaGetSymbolAddress((void**)&headb, g_headb);
    cudaGetSymbolAddress((void**)&head_out, g_head_out);
    cudaGetSymbolAddress((void**)&part, g_part);
    cudaGetSymbolAddress((void**)&sc80, g_scores80);
    cudaGetSymbolAddress((void**)&boxes, g_boxes);
    cudaGetSymbolAddress((void**)&sboxes, g_sorted_boxes);
    cudaGetSymbolAddress((void**)&sflat, g_sflat);

    // fused transpose: 2100+525+132+33 = 2790 HW tiles, 8 channel tiles
    nchw2nhwc_all_kernel<<<dim3(2790, 8), dim3(32, 8)>>>(f0, f1, f2, f3,
                                                         f0t, f1t, f2t, f3t);

    build_head_kernel<<<(NHEAD * FC + 255) / 256, 256>>>(cls_w, reg_w, cls_b, reg_b,
                                                         headw, headb);

    roi_align_kernel<<<N_PROP, 128>>>(f0t, f1t, f2t, f3t, props, roi_feats);

    // fc1: K=12544, Kc=3136  grid 8x8x4 = 256 CTAs
    gemm_bf16_splitk_kernel<<<dim3(FC / 128, (N_PROP + 127) / 128, SPLITK), 512>>>(
        roi_feats, fc1_w, part, N_PROP, FC, DFEAT / SPLITK, DFEAT);
    reduce_k_kernel<<<(N_PROP * FC + 255) / 256, 256>>>(part, fc1_b, h1, N_PROP, FC, 1, 1);

    // fc2: K=1024, Kc=256
    gemm_bf16_splitk_kernel<<<dim3(FC / 128, (N_PROP + 127) / 128, SPLITK), 512>>>(
        h1, fc2_w, part, N_PROP, FC, FC / SPLITK, FC);
    reduce_k_kernel<<<(N_PROP * FC + 255) / 256, 256>>>(part, fc2_b, h2, N_PROP, FC, 1, 1);

    // head: N=401, K=1024, Kc=256  grid 4x8x4
    gemm_bf16_splitk_kernel<<<dim3((NHEAD + 127) / 128, (N_PROP + 127) / 128, SPLITK), 512>>>(
        h2, headw, part, N_PROP, NHEAD, FC / SPLITK, FC);
    reduce_k_kernel<<<(N_PROP * NHEAD + 255) / 256, 256>>>(part, headb, head_out,
                                                           N_PROP, NHEAD, 0, 0);

    head_kernel<<<N_PROP, 128>>>(head_out, props, sc80, boxes);
    nms_kernel<<<NUM_CLASSES, 256>>>(sc80, boxes, sboxes, sflat);
    compact_kernel<<<80, 256>>>(sflat);
    topk_kernel<<<1, 256>>>(sboxes, out, out_size);
}